// round 6
// baseline (speedup 1.0000x reference)
#include <cuda_runtime.h>
#include <math.h>

#define NN 50000
#define NE 800000
#define L  64
#define NB32 ((NN + 31) / 32)

typedef unsigned long long u64;

__device__ __forceinline__ u64 pack2(float a, float b){
    u64 r; asm("mov.b64 %0, {%1, %2};" : "=l"(r) : "f"(a), "f"(b)); return r;
}
__device__ __forceinline__ void unpack2(u64 v, float& a, float& b){
    asm("mov.b64 {%0, %1}, %2;" : "=f"(a), "=f"(b) : "l"(v));
}
__device__ __forceinline__ void ffma2(u64& acc, u64 a, u64 b){
    asm("fma.rn.f32x2 %0, %1, %2, %0;" : "+l"(acc) : "l"(a), "l"(b));
}

// ------------- device scratch (statics are zero-initialized; k_fin re-zeroes) -------------
__device__ float  g_H [NN*L];
__device__ float  g_H0[NN*L];
__device__ float  g_Pt[NN*L];
__device__ float  g_Qt[NN*L];
__device__ float  g_Pf[NN*L];
__device__ float  g_Qf[NN*L];
__device__ float  g_mt[NN*L];
__device__ float  g_mf[NN*L];
__device__ float  g_U [NN];
__device__ int    g_rowptr[NN+1];
__device__ int    g_colptr[NN+1];
__device__ int    g_cntr[NN];
__device__ int    g_cntc[NN];
__device__ float4 g_rowE4[NE];
__device__ float4 g_colE4[NE];
__device__ float  g_rowA[NE];
__device__ int    g_rowJ[NE];
__device__ double g_loss;

__device__ __forceinline__ float sigf(float v){ return 1.f/(1.f+__expf(-v)); }

// ---------------- CSR build ----------------
__global__ void k_hist(const int* __restrict__ ei){
    int e = blockIdx.x*blockDim.x + threadIdx.x;
    if(e < NE){
        atomicAdd(&g_cntr[ei[e]], 1);
        atomicAdd(&g_cntc[ei[NE+e]], 1);
    }
}

__device__ void scan_one(int* cnt, int* ptr, int* part){
    const int C = (NN + 1023)/1024;
    int t = threadIdx.x;
    int s = 0;
    for(int k=0;k<C;k++){ int id=t*C+k; if(id<NN) s += cnt[id]; }
    part[t] = s; __syncthreads();
    for(int off=1; off<1024; off<<=1){
        int v = (t>=off)? part[t-off] : 0;
        __syncthreads();
        part[t] += v;
        __syncthreads();
    }
    int run = (t==0)? 0 : part[t-1];
    for(int k=0;k<C;k++){
        int id = t*C+k;
        if(id<NN){ int v=cnt[id]; ptr[id]=run; run+=v; cnt[id]=0; }
    }
    if(t==0) ptr[NN] = part[1023];
    __syncthreads();
}

__global__ void k_scan(){
    __shared__ int part[1024];
    scan_one(g_cntr, g_rowptr, part);
    scan_one(g_cntc, g_colptr, part);
}

__global__ void k_scatter(const int* __restrict__ ei, const float* __restrict__ ea,
                          const float* __restrict__ aij){
    int e = blockIdx.x*blockDim.x + threadIdx.x;
    if(e >= NE) return;
    int r = ei[e], c = ei[NE+e];
    float a0 = ea[3*e], a1 = ea[3*e+1], a2 = ea[3*e+2];
    int pr = atomicAdd(&g_cntr[r], 1);
    int p  = g_rowptr[r] + pr;
    g_rowE4[p] = make_float4(a0,a1,a2,__int_as_float(c));
    g_rowA[p]  = aij[e];
    g_rowJ[p]  = c;
    int pc = atomicAdd(&g_cntc[c], 1);
    int q  = g_colptr[c] + pc;
    g_colE4[q] = make_float4(a0,a1,a2,__int_as_float(r));
}

// ---------------- encoder: x -> H0, H ----------------
__global__ __launch_bounds__(256) void k_enc0(const float* __restrict__ x,
        const float* __restrict__ eW1, const float* __restrict__ eb1,
        const float* __restrict__ eW2, const float* __restrict__ eb2){
    __shared__ float sW[L*L];
    __shared__ float sh[8][4][L];
    int tid = threadIdx.x;
    for(int i=tid;i<L*L;i+=256) sW[i]=eW2[i];
    __syncthreads();
    int lane = tid&31, w = tid>>5, c0 = 2*lane;
    int nb = blockIdx.x*32 + w*4;
    float w1a=eW1[c0], w1b=eW1[c0+1], b1a=eb1[c0], b1b=eb1[c0+1];
    float b2a=eb2[c0], b2b=eb2[c0+1];
    bool val[4];
    #pragma unroll
    for(int v=0;v<4;v++){
        int n = nb+v; val[v] = (n<NN);
        float xv = val[v]? x[n] : 0.f;
        sh[w][v][c0]   = fmaxf(fmaf(xv,w1a,b1a),0.f);
        sh[w][v][c0+1] = fmaxf(fmaf(xv,w1b,b1b),0.f);
    }
    __syncwarp();
    u64 acc[4];
    #pragma unroll
    for(int v=0;v<4;v++) acc[v] = pack2(b2a,b2b);
    for(int k=0;k<L;k++){
        u64 wv = *(const u64*)&sW[k*L+c0];
        #pragma unroll
        for(int v=0;v<4;v++){ float s=sh[w][v][k]; ffma2(acc[v], wv, pack2(s,s)); }
    }
    #pragma unroll
    for(int v=0;v<4;v++) if(val[v]){
        int n = nb+v; float a,b; unpack2(acc[v],a,b);
        g_H0[n*L+c0]=a; g_H0[n*L+c0+1]=b;
        g_H [n*L+c0]=a; g_H [n*L+c0+1]=b;
    }
}

// ---------------- P/Q precompute (both phis), FFMA2 ----------------
#define PREP_SMEM ((4*L*L + 32*L)*4)
__global__ __launch_bounds__(256) void k_prep(
        const float* __restrict__ ptW1, const float* __restrict__ ptb1,
        const float* __restrict__ pfW1, const float* __restrict__ pfb1){
    extern __shared__ float sm[];
    float* Wat = sm;            // ptW1 rows 0..63
    float* Wbt = sm + L*L;      // ptW1 rows 64..127
    float* Waf = sm + 2*L*L;
    float* Wbf = sm + 3*L*L;
    float* stg = sm + 4*L*L;    // [32][64] H rows
    int tid = threadIdx.x;
    for(int i=tid;i<L*L;i+=256){
        Wat[i]=ptW1[i]; Wbt[i]=ptW1[L*L+i];
        Waf[i]=pfW1[i]; Wbf[i]=pfW1[L*L+i];
    }
    int lane = tid&31, w = tid>>5, c0 = 2*lane;
    int nb = blockIdx.x*32 + w*4;
    bool val[4];
    #pragma unroll
    for(int v=0;v<4;v++){
        int n = nb+v; val[v] = (n<NN);
        float h0 = val[v]? g_H[n*L+c0]   : 0.f;
        float h1 = val[v]? g_H[n*L+c0+1] : 0.f;
        stg[(w*4+v)*L + c0]   = h0;
        stg[(w*4+v)*L + c0+1] = h1;
    }
    __syncthreads();
    u64 pt[4],qt[4],pf[4],qf[4];
    float bt0=ptb1[c0], bt1=ptb1[c0+1], bf0=pfb1[c0], bf1=pfb1[c0+1];
    #pragma unroll
    for(int v=0;v<4;v++){ pt[v]=pack2(bt0,bt1); pf[v]=pack2(bf0,bf1); qt[v]=0ULL; qf[v]=0ULL; }
    for(int k=0;k<L;k++){
        u64 wat = *(const u64*)&Wat[k*L+c0];
        u64 wbt = *(const u64*)&Wbt[k*L+c0];
        u64 waf = *(const u64*)&Waf[k*L+c0];
        u64 wbf = *(const u64*)&Wbf[k*L+c0];
        #pragma unroll
        for(int v=0;v<4;v++){
            float h = stg[(w*4+v)*L + k];
            u64 h2 = pack2(h,h);
            ffma2(pt[v], wat, h2); ffma2(qt[v], wbt, h2);
            ffma2(pf[v], waf, h2); ffma2(qf[v], wbf, h2);
        }
    }
    #pragma unroll
    for(int v=0;v<4;v++) if(val[v]){
        int n = nb+v; float a,b;
        unpack2(pt[v],a,b); g_Pt[n*L+c0]=a; g_Pt[n*L+c0+1]=b;
        unpack2(qt[v],a,b); g_Qt[n*L+c0]=a; g_Qt[n*L+c0+1]=b;
        unpack2(pf[v],a,b); g_Pf[n*L+c0]=a; g_Pf[n*L+c0+1]=b;
        unpack2(qf[v],a,b); g_Qf[n*L+c0]=a; g_Qf[n*L+c0+1]=b;
    }
}

// ---------------- edge aggregation + W2 fold ----------------
__global__ __launch_bounds__(256) void k_aggr(
        const int* __restrict__ ptr, const float4* __restrict__ e4,
        const float* __restrict__ P, const float* __restrict__ Q,
        const float* __restrict__ W1full, const float* __restrict__ b2,
        const float* __restrict__ W2, float* __restrict__ out){
    __shared__ float sW2[L*L];
    __shared__ float sWe[3*L];
    __shared__ float sS[8][4][L];
    int tid = threadIdx.x;
    for(int i=tid;i<L*L;i+=256) sW2[i]=W2[i];
    for(int i=tid;i<3*L;i+=256) sWe[i]=W1full[2*L*L + i]; // rows 128..130
    __syncthreads();
    int lane = tid&31, w = tid>>5, c0 = 2*lane;
    int nb = blockIdx.x*32 + w*4;
    float we0a=sWe[c0],     we0b=sWe[c0+1];
    float we1a=sWe[L+c0],   we1b=sWe[L+c0+1];
    float we2a=sWe[2*L+c0], we2b=sWe[2*L+c0+1];
    float degv[4]; bool val[4];
    #pragma unroll
    for(int v=0;v<4;v++){
        int n = nb+v; val[v] = (n<NN);
        float acc0=0.f, acc1=0.f; int cnt=0;
        if(val[v]){
            float base0 = P[n*L+c0], base1 = P[n*L+c0+1];
            int s = ptr[n], e = ptr[n+1];
            for(int p=s; p<e; p++){
                float4 E = e4[p];
                int j = __float_as_int(E.w);
                if(j == n) continue;
                cnt++;
                float2 q = *(const float2*)&Q[j*L+c0];
                float pre0 = base0 + q.x + E.x*we0a + E.y*we1a + E.z*we2a;
                float pre1 = base1 + q.y + E.x*we0b + E.y*we1b + E.z*we2b;
                acc0 += fmaxf(pre0, 0.f);
                acc1 += fmaxf(pre1, 0.f);
            }
        }
        sS[w][v][c0]=acc0; sS[w][v][c0+1]=acc1; degv[v]=(float)cnt;
    }
    __syncwarp();
    float b2a=b2[c0], b2b=b2[c0+1];
    u64 o[4];
    #pragma unroll
    for(int v=0;v<4;v++) o[v] = pack2(degv[v]*b2a, degv[v]*b2b);
    for(int k=0;k<L;k++){
        u64 wv = *(const u64*)&sW2[k*L+c0];
        #pragma unroll
        for(int v=0;v<4;v++){ float s=sS[w][v][k]; ffma2(o[v], wv, pack2(s,s)); }
    }
    #pragma unroll
    for(int v=0;v<4;v++) if(val[v]){
        int n = nb+v; float a,b; unpack2(o[v],a,b);
        out[n*L+c0]=a; out[n*L+c0+1]=b;
    }
}

// ---------------- fused node update: chunk-streamed weights, ~100KB smem -> 2 blocks/SM ----------------
#define KC 65
#define NODE_SMEM ((3*KC*L + L*L + 32*196 + 32*L)*4)
__global__ __launch_bounds__(256) void k_node(
        const int* __restrict__ tags, const float* __restrict__ prb,
        const float* __restrict__ zkW, const float* __restrict__ zkb,
        const float* __restrict__ rkW, const float* __restrict__ rkb,
        const float* __restrict__ cW,  const float* __restrict__ cb,
        const float* __restrict__ dW1, const float* __restrict__ db1,
        const float* __restrict__ dW2, const float* __restrict__ db2,
        const float* __restrict__ eW1, const float* __restrict__ eb1,
        const float* __restrict__ eW2, const float* __restrict__ eb2){
    extern __shared__ float sm[];
    float* sbuf  = sm;                    // 3*KC*64 chunk buffer (also dW1/eW2 later)
    float* scwlo = sbuf + 3*KC*L;         // cW rows 0..63 (64*64)
    float* stgA  = scwlo + L*L;           // [32][196]
    float* stgB  = stgA + 32*196;         // [32][64]
    __shared__ float sdW2[L], sdb1[L], sE1[L], sEb1[L], szb[L], srb[L], scb[L], sEb2[L];
    __shared__ double red[8];
    int tid = threadIdx.x;
    if(tid<L){ sdW2[tid]=dW2[tid]; sdb1[tid]=db1[tid]; sE1[tid]=eW1[tid]; sEb1[tid]=eb1[tid];
               szb[tid]=zkb[tid]; srb[tid]=rkb[tid]; scb[tid]=cb[tid]; sEb2[tid]=eb2[tid]; }
    for(int i=tid;i<L*L;i+=256) scwlo[i]=cW[i];
    int lane = tid&31, w = tid>>5, c0 = 2*lane;
    int nb = blockIdx.x*32 + w*4;
    float db2v = db2[0];
    bool val[4];
    // stage cat = [H, mt, mf, prb]
    #pragma unroll
    for(int v=0;v<4;v++){
        int n = nb+v; val[v] = (n<NN);
        float* A = stgA + (w*4+v)*196;
        if(val[v]){
            A[c0]       = g_H [n*L+c0];  A[c0+1]     = g_H [n*L+c0+1];
            A[64+c0]    = g_mt[n*L+c0];  A[64+c0+1]  = g_mt[n*L+c0+1];
            A[128+c0]   = g_mf[n*L+c0];  A[128+c0+1] = g_mf[n*L+c0+1];
            if(lane==0){ A[192]=prb[2*n]; A[193]=prb[2*n+1]; }
        } else {
            A[c0]=A[c0+1]=A[64+c0]=A[64+c0+1]=A[128+c0]=A[128+c0+1]=0.f;
            if(lane==0){ A[192]=0.f; A[193]=0.f; }
        }
    }
    u64 az[4],ar[4],ac[4];
    #pragma unroll
    for(int v=0;v<4;v++){ az[v]=0ULL; ar[v]=0ULL; ac[v]=0ULL; }
    // chunked gate GEMVs
    for(int ch=0; ch<3; ch++){
        int k0 = ch*KC;
        int nr = (194 - k0 < KC) ? (194 - k0) : KC;
        __syncthreads();
        for(int i=tid;i<nr*L;i+=256){
            int r = i>>6, cc = i&63;
            int g = (k0+r)*L+cc;
            sbuf[i]        = zkW[g];
            sbuf[KC*L+i]   = rkW[g];
            sbuf[2*KC*L+i] = cW[g];
        }
        __syncthreads();
        for(int kk=0;kk<nr;kk++){
            int k = k0+kk;
            u64 wz = *(const u64*)&sbuf[kk*L+c0];
            u64 wr = *(const u64*)&sbuf[(KC+kk)*L+c0];
            u64 wc = *(const u64*)&sbuf[(2*KC+kk)*L+c0];
            bool hi = (k >= 64);
            #pragma unroll
            for(int v=0;v<4;v++){
                float cv = stgA[(w*4+v)*196 + k];
                u64 c2 = pack2(cv,cv);
                ffma2(az[v], wz, c2); ffma2(ar[v], wr, c2);
                if(hi) ffma2(ac[v], wc, c2);
            }
        }
    }
    // activations
    float z0[4],z1[4];
    #pragma unroll
    for(int v=0;v<4;v++){
        float a0,a1,r0,r1;
        unpack2(az[v],a0,a1); unpack2(ar[v],r0,r1);
        z0[v]=sigf(a0+szb[c0]); z1[v]=sigf(a1+szb[c0+1]);
        float rr0=sigf(r0+srb[c0]), rr1=sigf(r1+srb[c0+1]);
        stgB[(w*4+v)*L+c0]=rr0; stgB[(w*4+v)*L+c0+1]=rr1;
    }
    __syncwarp();
    // corr reset part (k<64) with persistent cW rows
    for(int k=0;k<64;k++){
        u64 wc = *(const u64*)&scwlo[k*L+c0];
        #pragma unroll
        for(int v=0;v<4;v++){
            float rh = stgB[(w*4+v)*L+k] * stgA[(w*4+v)*196+k];
            ffma2(ac[v], wc, pack2(rh,rh));
        }
    }
    // Hn, write back, restage
    float Hn0[4], Hn1[4];
    #pragma unroll
    for(int v=0;v<4;v++){
        int n = nb+v;
        float* A = stgA + (w*4+v)*196;
        float cc0,cc1; unpack2(ac[v],cc0,cc1);
        float co0 = tanhf(cc0+scb[c0]);
        float co1 = tanhf(cc1+scb[c0+1]);
        float h0 = A[c0], h1 = A[c0+1];
        float hn0 = h0 + z0[v]*co0, hn1 = h1 + z1[v]*co1;
        if(val[v] && tags[n]==1){ hn0 = g_H0[n*L+c0]; hn1 = g_H0[n*L+c0+1]; }
        Hn0[v]=hn0; Hn1[v]=hn1;
        A[c0]=hn0; A[c0+1]=hn1;
        if(val[v]){ g_H[n*L+c0]=hn0; g_H[n*L+c0+1]=hn1; }
    }
    // load dW1 + eW2 into sbuf (reuse)
    __syncthreads();
    for(int i=tid;i<L*L;i+=256){ sbuf[i]=dW1[i]; sbuf[L*L+i]=eW2[i]; }
    __syncthreads();
    float* sdW1 = sbuf;
    float* seW2 = sbuf + L*L;
    // decoder: U = relu(Hn@dW1+db1)@dW2 + db2
    u64 ad[4];
    #pragma unroll
    for(int v=0;v<4;v++) ad[v]=pack2(sdb1[c0],sdb1[c0+1]);
    for(int k=0;k<L;k++){
        u64 wd = *(const u64*)&sdW1[k*L+c0];
        #pragma unroll
        for(int v=0;v<4;v++){
            float hk = stgA[(w*4+v)*196 + k];
            ffma2(ad[v], wd, pack2(hk,hk));
        }
    }
    float Uv[4];
    #pragma unroll
    for(int v=0;v<4;v++){
        float d0,d1; unpack2(ad[v],d0,d1);
        float pu = fmaxf(d0,0.f)*sdW2[c0] + fmaxf(d1,0.f)*sdW2[c0+1];
        for(int o=16;o;o>>=1) pu += __shfl_xor_sync(0xffffffffu, pu, o);
        Uv[v] = pu + db2v;
        int n = nb+v;
        if(val[v] && lane==0) g_U[n] = Uv[v];
        float eh0 = fmaxf(fmaf(Uv[v],sE1[c0],sEb1[c0]),0.f);
        float eh1 = fmaxf(fmaf(Uv[v],sE1[c0+1],sEb1[c0+1]),0.f);
        stgB[(w*4+v)*L+c0]=eh0; stgB[(w*4+v)*L+c0+1]=eh1;
    }
    __syncwarp();
    // enc(U): 64x64 GEMV
    u64 ae[4];
    #pragma unroll
    for(int v=0;v<4;v++) ae[v]=pack2(sEb2[c0],sEb2[c0+1]);
    for(int k=0;k<L;k++){
        u64 we = *(const u64*)&seW2[k*L+c0];
        #pragma unroll
        for(int v=0;v<4;v++){
            float ek = stgB[(w*4+v)*L+k];
            ffma2(ae[v], we, pack2(ek,ek));
        }
    }
    float encS = 0.f;
    #pragma unroll
    for(int v=0;v<4;v++){
        float* A = stgA + (w*4+v)*196;
        float e0,e1; unpack2(ae[v],e0,e1);
        if(val[v]){
            float d0 = e0-Hn0[v], d1 = e1-Hn1[v];
            encS += d0*d0 + d1*d1;
        }
        A[64+c0]=e0; A[64+c0+1]=e1;   // stash enc for autoenc pass
    }
    __syncwarp();
    // autoenc: dec(enc)
    u64 ag[4];
    #pragma unroll
    for(int v=0;v<4;v++) ag[v]=pack2(sdb1[c0],sdb1[c0+1]);
    for(int k=0;k<L;k++){
        u64 wd = *(const u64*)&sdW1[k*L+c0];
        #pragma unroll
        for(int v=0;v<4;v++){
            float ek = stgA[(w*4+v)*196 + 64 + k];
            ffma2(ag[v], wd, pack2(ek,ek));
        }
    }
    float autoS = 0.f;
    #pragma unroll
    for(int v=0;v<4;v++){
        float g0,g1; unpack2(ag[v],g0,g1);
        float pa = fmaxf(g0,0.f)*sdW2[c0] + fmaxf(g1,0.f)*sdW2[c0+1];
        for(int o=16;o;o>>=1) pa += __shfl_xor_sync(0xffffffffu, pa, o);
        float aout = pa + db2v;
        if(val[v] && lane==0){ float d = aout - Uv[v]; autoS += d*d; }
    }
    // loss reduction: enc_loss/(N*64) + autoenc_loss/N
    float tot = encS;
    for(int o=16;o;o>>=1) tot += __shfl_xor_sync(0xffffffffu, tot, o);
    float at = autoS;
    for(int o=16;o;o>>=1) at += __shfl_xor_sync(0xffffffffu, at, o);
    if(lane==0) red[w] = (double)tot/((double)NN*64.0) + (double)at/(double)NN;
    __syncthreads();
    if(tid==0){
        double s = 0.0;
        for(int i=0;i<8;i++) s += red[i];
        atomicAdd(&g_loss, s);
    }
}

// ---------------- residual loss: U staged in smem, gather via LDS ----------------
#define RES_SMEM (NN*4)
__global__ __launch_bounds__(256) void k_res(const float* __restrict__ y, float wgt){
    extern __shared__ float sU[];
    __shared__ double red[8];
    int tid = threadIdx.x;
    for(int i=tid;i<NN;i+=256) sU[i] = g_U[i];
    __syncthreads();
    int lane = tid&31, w = tid>>5;
    int wid = blockIdx.x*8 + w;
    int nwarps = gridDim.x*8;
    float ls = 0.f;
    for(int n = wid; n < NN; n += nwarps){
        int s = g_rowptr[n], e = g_rowptr[n+1];
        float part = 0.f;
        for(int p = s+lane; p < e; p += 32){
            part += g_rowA[p] * sU[g_rowJ[p]];
        }
        for(int o=16;o;o>>=1) part += __shfl_xor_sync(0xffffffffu, part, o);
        if(lane==0){ float d = part - y[n]; ls += d*d; }
    }
    for(int o=16;o;o>>=1) ls += __shfl_xor_sync(0xffffffffu, ls, o);
    if(lane==0) red[w] = (double)ls;
    __syncthreads();
    if(threadIdx.x==0){
        double s=0.0; for(int i=0;i<8;i++) s+=red[i];
        atomicAdd(&g_loss, s * (double)wgt / (double)NN);
    }
}

// ---------------- finalize + reset state for next graph replay ----------------
__global__ void k_fin(float* __restrict__ out, int out_size){
    int i = blockIdx.x*blockDim.x + threadIdx.x;
    if(i < NN && i < out_size) out[i] = g_U[i];
    if(i == NN){
        if(i < out_size) out[NN] = (float)g_loss;
        g_loss = 0.0;
    }
    if(i < NN){ g_cntr[i]=0; g_cntc[i]=0; }
}

extern "C" void kernel_launch(void* const* d_in, const int* in_sizes, int n_in,
                              void* d_out, int out_size){
    const float* x    = (const float*)d_in[0];
    const float* y    = (const float*)d_in[2];
    const int*   tags = (const int*)  d_in[3];
    const int*   ei   = (const int*)  d_in[4];
    const float* ea   = (const float*)d_in[5];
    const float* aij  = (const float*)d_in[6];
    const float* prb  = (const float*)d_in[7];
    const float* ptW1 = (const float*)d_in[8];
    const float* ptb1 = (const float*)d_in[9];
    const float* ptW2 = (const float*)d_in[10];
    const float* ptb2 = (const float*)d_in[11];
    const float* pfW1 = (const float*)d_in[12];
    const float* pfb1 = (const float*)d_in[13];
    const float* pfW2 = (const float*)d_in[14];
    const float* pfb2 = (const float*)d_in[15];
    const float* zkW  = (const float*)d_in[16];
    const float* zkb  = (const float*)d_in[17];
    const float* rkW  = (const float*)d_in[18];
    const float* rkb  = (const float*)d_in[19];
    const float* cW   = (const float*)d_in[20];
    const float* cb   = (const float*)d_in[21];
    const float* eW1  = (const float*)d_in[22];
    const float* eb1  = (const float*)d_in[23];
    const float* eW2  = (const float*)d_in[24];
    const float* eb2  = (const float*)d_in[25];
    const float* dW1  = (const float*)d_in[26];
    const float* db1  = (const float*)d_in[27];
    const float* dW2  = (const float*)d_in[28];
    const float* db2  = (const float*)d_in[29];

    int smc = 148;
    cudaDeviceGetAttribute(&smc, cudaDevAttrMultiProcessorCount, 0);

    cudaFuncSetAttribute(k_prep, cudaFuncAttributeMaxDynamicSharedMemorySize, PREP_SMEM);
    cudaFuncSetAttribute(k_node, cudaFuncAttributeMaxDynamicSharedMemorySize, NODE_SMEM);
    cudaFuncSetAttribute(k_res,  cudaFuncAttributeMaxDynamicSharedMemorySize, RES_SMEM);

    // device addresses of scratch symbols (host must use cudaGetSymbolAddress)
    int *rowptr, *colptr;
    float4 *rowE4, *colE4;
    float *Pt, *Qt, *Pf, *Qf, *mt, *mf;
    cudaGetSymbolAddress((void**)&rowptr, g_rowptr);
    cudaGetSymbolAddress((void**)&colptr, g_colptr);
    cudaGetSymbolAddress((void**)&rowE4,  g_rowE4);
    cudaGetSymbolAddress((void**)&colE4,  g_colE4);
    cudaGetSymbolAddress((void**)&Pt, g_Pt);
    cudaGetSymbolAddress((void**)&Qt, g_Qt);
    cudaGetSymbolAddress((void**)&Pf, g_Pf);
    cudaGetSymbolAddress((void**)&Qf, g_Qf);
    cudaGetSymbolAddress((void**)&mt, g_mt);
    cudaGetSymbolAddress((void**)&mf, g_mf);

    // Order chosen so launch idx 3 (the ncu-profiled slot) is k_prep.
    k_enc0<<<NB32, 256>>>(x, eW1, eb1, eW2, eb2);                 // 0
    k_hist<<<(NE+255)/256, 256>>>(ei);                            // 1
    k_scan<<<1, 1024>>>();                                        // 2
    k_prep<<<NB32, 256, PREP_SMEM>>>(ptW1, ptb1, pfW1, pfb1);     // 3 (profiled)
    k_scatter<<<(NE+255)/256, 256>>>(ei, ea, aij);                // 4

    const float gammaw[2] = {0.9f, 1.0f};
    for(int step=0; step<2; step++){
        if(step > 0)
            k_prep<<<NB32, 256, PREP_SMEM>>>(ptW1, ptb1, pfW1, pfb1);
        // mess_to: i = col (col-CSR), neighbor j = row
        k_aggr<<<NB32, 256>>>(colptr, colE4, Pt, Qt, ptW1, ptb2, ptW2, mt);
        // mess_from: i = row (row-CSR), neighbor j = col
        k_aggr<<<NB32, 256>>>(rowptr, rowE4, Pf, Qf, pfW1, pfb2, pfW2, mf);
        k_node<<<NB32, 256, NODE_SMEM>>>(tags, prb, zkW, zkb, rkW, rkb, cW, cb,
                                         dW1, db1, dW2, db2, eW1, eb1, eW2, eb2);
        k_res<<<smc, 256, RES_SMEM>>>(y, gammaw[step]);
    }
    k_fin<<<(NN+256)/256, 256>>>((float*)d_out, out_size);
}

// round 7
// speedup vs baseline: 1.0187x; 1.0187x over previous
#include <cuda_runtime.h>
#include <math.h>

#define NN 50000
#define NE 800000
#define L  64
#define NB32 ((NN + 31) / 32)
#define NB64 ((NN + 63) / 64)

typedef unsigned long long u64;

__device__ __forceinline__ u64 pack2(float a, float b){
    u64 r; asm("mov.b64 %0, {%1, %2};" : "=l"(r) : "f"(a), "f"(b)); return r;
}
__device__ __forceinline__ void unpack2(u64 v, float& a, float& b){
    asm("mov.b64 {%0, %1}, %2;" : "=f"(a), "=f"(b) : "l"(v));
}
__device__ __forceinline__ void ffma2(u64& acc, u64 a, u64 b){
    asm("fma.rn.f32x2 %0, %1, %2, %0;" : "+l"(acc) : "l"(a), "l"(b));
}

// ------------- device scratch (statics zero-initialized; k_fin re-zeroes) -------------
__device__ float  g_H [NN*L];
__device__ float  g_H0[NN*L];
__device__ float  g_Pt[NN*L];
__device__ float  g_Qt[NN*L];
__device__ float  g_Pf[NN*L];
__device__ float  g_Qf[NN*L];
__device__ float  g_mt[NN*L];
__device__ float  g_mf[NN*L];
__device__ float  g_U [NN];
__device__ int    g_rowptr[NN+1];
__device__ int    g_colptr[NN+1];
__device__ int    g_cntr[NN];
__device__ int    g_cntc[NN];
__device__ float4 g_rowE4[NE];
__device__ float4 g_colE4[NE];
__device__ float  g_rowA[NE];
__device__ double g_loss;

__device__ __forceinline__ float sigf(float v){ return 1.f/(1.f+__expf(-v)); }

// ---------------- CSR build ----------------
__global__ void k_hist(const int* __restrict__ ei){
    int e = blockIdx.x*blockDim.x + threadIdx.x;
    if(e < NE){
        atomicAdd(&g_cntr[ei[e]], 1);
        atomicAdd(&g_cntc[ei[NE+e]], 1);
    }
}

__device__ void scan_one(int* cnt, int* ptr, int* part){
    const int C = (NN + 1023)/1024;
    int t = threadIdx.x;
    int s = 0;
    for(int k=0;k<C;k++){ int id=t*C+k; if(id<NN) s += cnt[id]; }
    part[t] = s; __syncthreads();
    for(int off=1; off<1024; off<<=1){
        int v = (t>=off)? part[t-off] : 0;
        __syncthreads();
        part[t] += v;
        __syncthreads();
    }
    int run = (t==0)? 0 : part[t-1];
    for(int k=0;k<C;k++){
        int id = t*C+k;
        if(id<NN){ int v=cnt[id]; ptr[id]=run; run+=v; cnt[id]=0; }
    }
    if(t==0) ptr[NN] = part[1023];
    __syncthreads();
}

__global__ void k_scan(){
    __shared__ int part[1024];
    scan_one(g_cntr, g_rowptr, part);
    scan_one(g_cntc, g_colptr, part);
}

__global__ void k_scatter(const int* __restrict__ ei, const float* __restrict__ ea,
                          const float* __restrict__ aij){
    int e = blockIdx.x*blockDim.x + threadIdx.x;
    if(e >= NE) return;
    int r = ei[e], c = ei[NE+e];
    float a0 = ea[3*e], a1 = ea[3*e+1], a2 = ea[3*e+2];
    int pr = atomicAdd(&g_cntr[r], 1);
    int p  = g_rowptr[r] + pr;
    g_rowE4[p] = make_float4(a0,a1,a2,__int_as_float(c));
    g_rowA[p]  = aij[e];
    int pc = atomicAdd(&g_cntc[c], 1);
    int q  = g_colptr[c] + pc;
    g_colE4[q] = make_float4(a0,a1,a2,__int_as_float(r));
}

// ---------------- encoder: x -> H0, H ----------------
__global__ __launch_bounds__(256) void k_enc0(const float* __restrict__ x,
        const float* __restrict__ eW1, const float* __restrict__ eb1,
        const float* __restrict__ eW2, const float* __restrict__ eb2){
    __shared__ float sW[L*L];
    __shared__ float sh[8][4][L];
    int tid = threadIdx.x;
    for(int i=tid;i<L*L;i+=256) sW[i]=eW2[i];
    __syncthreads();
    int lane = tid&31, w = tid>>5, c0 = 2*lane;
    int nb = blockIdx.x*32 + w*4;
    float w1a=eW1[c0], w1b=eW1[c0+1], b1a=eb1[c0], b1b=eb1[c0+1];
    float b2a=eb2[c0], b2b=eb2[c0+1];
    bool val[4];
    #pragma unroll
    for(int v=0;v<4;v++){
        int n = nb+v; val[v] = (n<NN);
        float xv = val[v]? x[n] : 0.f;
        sh[w][v][c0]   = fmaxf(fmaf(xv,w1a,b1a),0.f);
        sh[w][v][c0+1] = fmaxf(fmaf(xv,w1b,b1b),0.f);
    }
    __syncwarp();
    u64 acc[4];
    #pragma unroll
    for(int v=0;v<4;v++) acc[v] = pack2(b2a,b2b);
    for(int k=0;k<L;k++){
        u64 wv = *(const u64*)&sW[k*L+c0];
        #pragma unroll
        for(int v=0;v<4;v++){ float s=sh[w][v][k]; ffma2(acc[v], wv, pack2(s,s)); }
    }
    #pragma unroll
    for(int v=0;v<4;v++) if(val[v]){
        int n = nb+v; float a,b; unpack2(acc[v],a,b);
        g_H0[n*L+c0]=a; g_H0[n*L+c0+1]=b;
        g_H [n*L+c0]=a; g_H [n*L+c0+1]=b;
    }
}

// ---------------- P/Q precompute: split by direction, 8 nodes/warp ----------------
#define PREP_SMEM ((2*L*L + 64*L)*4)
__global__ __launch_bounds__(256) void k_prep(
        const float* __restrict__ ptW1, const float* __restrict__ ptb1,
        const float* __restrict__ pfW1, const float* __restrict__ pfb1){
    extern __shared__ float sm[];
    float* Wa  = sm;          // W1 rows 0..63  (h_i part)
    float* Wb  = sm + L*L;    // W1 rows 64..127 (h_j part)
    float* stg = sm + 2*L*L;  // [64][64] H rows
    bool toDir = (blockIdx.x < NB64);
    int bb = toDir ? blockIdx.x : blockIdx.x - NB64;
    const float* W1  = toDir ? ptW1 : pfW1;
    const float* bia = toDir ? ptb1 : pfb1;
    float* Pout = toDir ? g_Pt : g_Pf;
    float* Qout = toDir ? g_Qt : g_Qf;
    int tid = threadIdx.x;
    for(int i=tid;i<L*L;i+=256){ Wa[i]=W1[i]; Wb[i]=W1[L*L+i]; }
    int lane = tid&31, w = tid>>5, c0 = 2*lane;
    int i0 = w*8, nb = bb*64 + i0;
    bool val[8];
    #pragma unroll
    for(int v=0;v<8;v++){
        int n = nb+v; val[v] = (n<NN);
        float2 h = val[v]? *(const float2*)&g_H[n*L+c0] : make_float2(0.f,0.f);
        *(float2*)&stg[(i0+v)*L+c0] = h;
    }
    __syncthreads();
    u64 p[8], q[8];
    float b0 = bia[c0], b1v = bia[c0+1];
    #pragma unroll
    for(int v=0;v<8;v++){ p[v]=pack2(b0,b1v); q[v]=0ULL; }
    for(int k=0;k<L;k+=2){
        u64 wa0=*(const u64*)&Wa[k*L+c0],     wb0=*(const u64*)&Wb[k*L+c0];
        u64 wa1=*(const u64*)&Wa[(k+1)*L+c0], wb1=*(const u64*)&Wb[(k+1)*L+c0];
        #pragma unroll
        for(int v=0;v<8;v++){
            u64 hh = *(const u64*)&stg[(i0+v)*L+k];
            float lo,hi; unpack2(hh,lo,hi);
            u64 a0=pack2(lo,lo), a1=pack2(hi,hi);
            ffma2(p[v],wa0,a0); ffma2(q[v],wb0,a0);
            ffma2(p[v],wa1,a1); ffma2(q[v],wb1,a1);
        }
    }
    #pragma unroll
    for(int v=0;v<8;v++) if(val[v]){
        int n = nb+v; float a,b;
        unpack2(p[v],a,b); Pout[n*L+c0]=a; Pout[n*L+c0+1]=b;
        unpack2(q[v],a,b); Qout[n*L+c0]=a; Qout[n*L+c0+1]=b;
    }
}

// ---------------- edge aggregation + W2 fold ----------------
__global__ __launch_bounds__(256) void k_aggr(
        const int* __restrict__ ptr, const float4* __restrict__ e4,
        const float* __restrict__ P, const float* __restrict__ Q,
        const float* __restrict__ W1full, const float* __restrict__ b2,
        const float* __restrict__ W2, float* __restrict__ out){
    __shared__ float sW2[L*L];
    __shared__ float sWe[3*L];
    __shared__ float sS[8][4][L];
    int tid = threadIdx.x;
    for(int i=tid;i<L*L;i+=256) sW2[i]=W2[i];
    for(int i=tid;i<3*L;i+=256) sWe[i]=W1full[2*L*L + i]; // rows 128..130
    __syncthreads();
    int lane = tid&31, w = tid>>5, c0 = 2*lane;
    int nb = blockIdx.x*32 + w*4;
    float we0a=sWe[c0],     we0b=sWe[c0+1];
    float we1a=sWe[L+c0],   we1b=sWe[L+c0+1];
    float we2a=sWe[2*L+c0], we2b=sWe[2*L+c0+1];
    float degv[4]; bool val[4];
    #pragma unroll
    for(int v=0;v<4;v++){
        int n = nb+v; val[v] = (n<NN);
        float acc0=0.f, acc1=0.f; int cnt=0;
        if(val[v]){
            float base0 = P[n*L+c0], base1 = P[n*L+c0+1];
            int s = ptr[n], e = ptr[n+1];
            for(int p=s; p<e; p++){
                float4 E = e4[p];
                int j = __float_as_int(E.w);
                if(j == n) continue;
                cnt++;
                float2 qv = *(const float2*)&Q[j*L+c0];
                float pre0 = base0 + qv.x + E.x*we0a + E.y*we1a + E.z*we2a;
                float pre1 = base1 + qv.y + E.x*we0b + E.y*we1b + E.z*we2b;
                acc0 += fmaxf(pre0, 0.f);
                acc1 += fmaxf(pre1, 0.f);
            }
        }
        sS[w][v][c0]=acc0; sS[w][v][c0+1]=acc1; degv[v]=(float)cnt;
    }
    __syncwarp();
    float b2a=b2[c0], b2b=b2[c0+1];
    u64 o[4];
    #pragma unroll
    for(int v=0;v<4;v++) o[v] = pack2(degv[v]*b2a, degv[v]*b2b);
    for(int k=0;k<L;k++){
        u64 wv = *(const u64*)&sW2[k*L+c0];
        #pragma unroll
        for(int v=0;v<4;v++){ float s=sS[w][v][k]; ffma2(o[v], wv, pack2(s,s)); }
    }
    #pragma unroll
    for(int v=0;v<4;v++) if(val[v]){
        int n = nb+v; float a,b; unpack2(o[v],a,b);
        out[n*L+c0]=a; out[n*L+c0+1]=b;
    }
}

// ---------------- fused node update: 64 nodes/block, 8 nodes/warp ----------------
#define NODE_SMEM ((3*194*L + 64*196 + 64*L)*4)
__global__ __launch_bounds__(256) void k_node(
        const int* __restrict__ tags, const float* __restrict__ prb,
        const float* __restrict__ zkW, const float* __restrict__ zkb,
        const float* __restrict__ rkW, const float* __restrict__ rkb,
        const float* __restrict__ cW,  const float* __restrict__ cb,
        const float* __restrict__ dW1, const float* __restrict__ db1,
        const float* __restrict__ dW2, const float* __restrict__ db2,
        const float* __restrict__ eW1, const float* __restrict__ eb1,
        const float* __restrict__ eW2, const float* __restrict__ eb2){
    extern __shared__ float sm[];
    float* szk  = sm;                 // 194*64
    float* srk  = szk + 194*L;
    float* scw  = srk + 194*L;
    float* stgA = scw + 194*L;        // [64][196]
    float* stgB = stgA + 64*196;      // [64][64]
    __shared__ float sdW2[L], sdb1[L], sE1[L], sEb1[L], szb[L], srb[L], scb[L], sEb2[L];
    __shared__ double red[8];
    int tid = threadIdx.x;
    for(int i=tid;i<194*L;i+=256){ szk[i]=zkW[i]; srk[i]=rkW[i]; scw[i]=cW[i]; }
    if(tid<L){ sdW2[tid]=dW2[tid]; sdb1[tid]=db1[tid]; sE1[tid]=eW1[tid]; sEb1[tid]=eb1[tid];
               szb[tid]=zkb[tid]; srb[tid]=rkb[tid]; scb[tid]=cb[tid]; sEb2[tid]=eb2[tid]; }
    int lane = tid&31, w = tid>>5, c0 = 2*lane;
    int i0 = w*8, nb = blockIdx.x*64 + i0;
    float db2v = db2[0];
    bool val[8];
    // stage cat = [H, mt, mf, prb]
    #pragma unroll
    for(int v=0;v<8;v++){
        int n = nb+v; val[v] = (n<NN);
        float* A = stgA + (i0+v)*196;
        if(val[v]){
            *(float2*)&A[c0]     = *(const float2*)&g_H [n*L+c0];
            *(float2*)&A[64+c0]  = *(const float2*)&g_mt[n*L+c0];
            *(float2*)&A[128+c0] = *(const float2*)&g_mf[n*L+c0];
            if(lane==0){ A[192]=prb[2*n]; A[193]=prb[2*n+1]; A[194]=0.f; A[195]=0.f; }
        } else {
            *(float2*)&A[c0]     = make_float2(0.f,0.f);
            *(float2*)&A[64+c0]  = make_float2(0.f,0.f);
            *(float2*)&A[128+c0] = make_float2(0.f,0.f);
            if(lane==0){ A[192]=0.f; A[193]=0.f; A[194]=0.f; A[195]=0.f; }
        }
    }
    __syncthreads();
    u64 az[8],ar[8],ac[8];
    #pragma unroll
    for(int v=0;v<8;v++){ az[v]=0ULL; ar[v]=0ULL; ac[v]=0ULL; }
    for(int k=0;k<64;k+=2){
        u64 wz0=*(const u64*)&szk[k*L+c0],     wr0=*(const u64*)&srk[k*L+c0];
        u64 wz1=*(const u64*)&szk[(k+1)*L+c0], wr1=*(const u64*)&srk[(k+1)*L+c0];
        #pragma unroll
        for(int v=0;v<8;v++){
            u64 cc = *(const u64*)&stgA[(i0+v)*196 + k];
            float lo,hi; unpack2(cc,lo,hi);
            u64 a0=pack2(lo,lo), a1=pack2(hi,hi);
            ffma2(az[v],wz0,a0); ffma2(ar[v],wr0,a0);
            ffma2(az[v],wz1,a1); ffma2(ar[v],wr1,a1);
        }
    }
    for(int k=64;k<194;k+=2){
        u64 wz0=*(const u64*)&szk[k*L+c0],     wr0=*(const u64*)&srk[k*L+c0],     wc0=*(const u64*)&scw[k*L+c0];
        u64 wz1=*(const u64*)&szk[(k+1)*L+c0], wr1=*(const u64*)&srk[(k+1)*L+c0], wc1=*(const u64*)&scw[(k+1)*L+c0];
        #pragma unroll
        for(int v=0;v<8;v++){
            u64 cc = *(const u64*)&stgA[(i0+v)*196 + k];
            float lo,hi; unpack2(cc,lo,hi);
            u64 a0=pack2(lo,lo), a1=pack2(hi,hi);
            ffma2(az[v],wz0,a0); ffma2(ar[v],wr0,a0); ffma2(ac[v],wc0,a0);
            ffma2(az[v],wz1,a1); ffma2(ar[v],wr1,a1); ffma2(ac[v],wc1,a1);
        }
    }
    // activations: z, r (r -> stgB)
    float z0[8],z1[8];
    #pragma unroll
    for(int v=0;v<8;v++){
        float a0,a1,r0,r1;
        unpack2(az[v],a0,a1); unpack2(ar[v],r0,r1);
        z0[v]=sigf(a0+szb[c0]); z1[v]=sigf(a1+szb[c0+1]);
        float rr0=sigf(r0+srb[c0]), rr1=sigf(r1+srb[c0+1]);
        stgB[(i0+v)*L+c0]=rr0; stgB[(i0+v)*L+c0+1]=rr1;
    }
    __syncwarp();
    // corr reset part (k<64)
    for(int k=0;k<64;k++){
        u64 wc = *(const u64*)&scw[k*L+c0];
        #pragma unroll
        for(int v=0;v<8;v++){
            float rh = stgB[(i0+v)*L+k] * stgA[(i0+v)*196+k];
            ffma2(ac[v], wc, pack2(rh,rh));
        }
    }
    // Hn, write back, restage
    float Hn0[8], Hn1[8];
    #pragma unroll
    for(int v=0;v<8;v++){
        int n = nb+v;
        float* A = stgA + (i0+v)*196;
        float cc0,cc1; unpack2(ac[v],cc0,cc1);
        float co0 = tanhf(cc0+scb[c0]);
        float co1 = tanhf(cc1+scb[c0+1]);
        float h0 = A[c0], h1 = A[c0+1];
        float hn0 = h0 + z0[v]*co0, hn1 = h1 + z1[v]*co1;
        if(val[v] && tags[n]==1){ hn0 = g_H0[n*L+c0]; hn1 = g_H0[n*L+c0+1]; }
        Hn0[v]=hn0; Hn1[v]=hn1;
        A[c0]=hn0; A[c0+1]=hn1;
        if(val[v]){ g_H[n*L+c0]=hn0; g_H[n*L+c0+1]=hn1; }
    }
    __syncwarp();
    // decoder: U = relu(Hn@dW1+db1)@dW2 + db2  (dW1 via LDG, L1-resident)
    u64 ad[8];
    #pragma unroll
    for(int v=0;v<8;v++) ad[v]=pack2(sdb1[c0],sdb1[c0+1]);
    for(int k=0;k<L;k++){
        u64 wd = __ldg((const u64*)&dW1[k*L+c0]);
        #pragma unroll
        for(int v=0;v<8;v++){
            float hk = stgA[(i0+v)*196 + k];
            ffma2(ad[v], wd, pack2(hk,hk));
        }
    }
    float Uv[8];
    #pragma unroll
    for(int v=0;v<8;v++){
        float d0,d1; unpack2(ad[v],d0,d1);
        float pu = fmaxf(d0,0.f)*sdW2[c0] + fmaxf(d1,0.f)*sdW2[c0+1];
        for(int o=16;o;o>>=1) pu += __shfl_xor_sync(0xffffffffu, pu, o);
        Uv[v] = pu + db2v;
        int n = nb+v;
        if(val[v] && lane==0) g_U[n] = Uv[v];
        float eh0 = fmaxf(fmaf(Uv[v],sE1[c0],sEb1[c0]),0.f);
        float eh1 = fmaxf(fmaf(Uv[v],sE1[c0+1],sEb1[c0+1]),0.f);
        stgB[(i0+v)*L+c0]=eh0; stgB[(i0+v)*L+c0+1]=eh1;
    }
    __syncwarp();
    // enc(U): 64x64 GEMV (eW2 via LDG)
    u64 ae[8];
    #pragma unroll
    for(int v=0;v<8;v++) ae[v]=pack2(sEb2[c0],sEb2[c0+1]);
    for(int k=0;k<L;k++){
        u64 we = __ldg((const u64*)&eW2[k*L+c0]);
        #pragma unroll
        for(int v=0;v<8;v++){
            float ek = stgB[(i0+v)*L+k];
            ffma2(ae[v], we, pack2(ek,ek));
        }
    }
    float encS = 0.f;
    #pragma unroll
    for(int v=0;v<8;v++){
        float* A = stgA + (i0+v)*196;
        float e0,e1; unpack2(ae[v],e0,e1);
        if(val[v]){
            float d0 = e0-Hn0[v], d1 = e1-Hn1[v];
            encS += d0*d0 + d1*d1;
        }
        A[64+c0]=e0; A[64+c0+1]=e1;   // stash enc for autoenc pass
    }
    __syncwarp();
    // autoenc: dec(enc)
    u64 ag[8];
    #pragma unroll
    for(int v=0;v<8;v++) ag[v]=pack2(sdb1[c0],sdb1[c0+1]);
    for(int k=0;k<L;k++){
        u64 wd = __ldg((const u64*)&dW1[k*L+c0]);
        #pragma unroll
        for(int v=0;v<8;v++){
            float ek = stgA[(i0+v)*196 + 64 + k];
            ffma2(ag[v], wd, pack2(ek,ek));
        }
    }
    float autoS = 0.f;
    #pragma unroll
    for(int v=0;v<8;v++){
        float g0,g1; unpack2(ag[v],g0,g1);
        float pa = fmaxf(g0,0.f)*sdW2[c0] + fmaxf(g1,0.f)*sdW2[c0+1];
        for(int o=16;o;o>>=1) pa += __shfl_xor_sync(0xffffffffu, pa, o);
        float aout = pa + db2v;
        if(val[v] && lane==0){ float d = aout - Uv[v]; autoS += d*d; }
    }
    // loss reduction: enc_loss/(N*64) + autoenc_loss/N
    float tot = encS;
    for(int o=16;o;o>>=1) tot += __shfl_xor_sync(0xffffffffu, tot, o);
    float at = autoS;
    for(int o=16;o;o>>=1) at += __shfl_xor_sync(0xffffffffu, at, o);
    if(lane==0) red[w] = (double)tot/((double)NN*64.0) + (double)at/(double)NN;
    __syncthreads();
    if(tid==0){
        double s = 0.0;
        for(int i=0;i<8;i++) s += red[i];
        atomicAdd(&g_loss, s);
    }
}

// ---------------- residual loss ----------------
__global__ __launch_bounds__(256) void k_res(const float* __restrict__ y, float wgt){
    __shared__ double red[8];
    int lane = threadIdx.x&31, w = threadIdx.x>>5;
    int wid = blockIdx.x*8 + w;
    int nwarps = gridDim.x*8;
    float ls = 0.f;
    for(int n = wid; n < NN; n += nwarps){
        int s = g_rowptr[n], e = g_rowptr[n+1];
        float part = 0.f;
        for(int p = s+lane; p < e; p += 32){
            int j = __float_as_int(g_rowE4[p].w);
            part += g_rowA[p] * g_U[j];
        }
        for(int o=16;o;o>>=1) part += __shfl_xor_sync(0xffffffffu, part, o);
        if(lane==0){ float d = part - y[n]; ls += d*d; }
    }
    for(int o=16;o;o>>=1) ls += __shfl_xor_sync(0xffffffffu, ls, o);
    if(lane==0) red[w] = (double)ls;
    __syncthreads();
    if(threadIdx.x==0){
        double s=0.0; for(int i=0;i<8;i++) s+=red[i];
        atomicAdd(&g_loss, s * (double)wgt / (double)NN);
    }
}

// ---------------- finalize + reset state for next replay ----------------
__global__ void k_fin(float* __restrict__ out, int out_size){
    int i = blockIdx.x*blockDim.x + threadIdx.x;
    if(i < NN && i < out_size) out[i] = g_U[i];
    if(i == NN){
        if(i < out_size) out[NN] = (float)g_loss;
        g_loss = 0.0;
    }
    if(i < NN){ g_cntr[i]=0; g_cntc[i]=0; }
}

extern "C" void kernel_launch(void* const* d_in, const int* in_sizes, int n_in,
                              void* d_out, int out_size){
    const float* x    = (const float*)d_in[0];
    const float* y    = (const float*)d_in[2];
    const int*   tags = (const int*)  d_in[3];
    const int*   ei   = (const int*)  d_in[4];
    const float* ea   = (const float*)d_in[5];
    const float* aij  = (const float*)d_in[6];
    const float* prb  = (const float*)d_in[7];
    const float* ptW1 = (const float*)d_in[8];
    const float* ptb1 = (const float*)d_in[9];
    const float* ptW2 = (const float*)d_in[10];
    const float* ptb2 = (const float*)d_in[11];
    const float* pfW1 = (const float*)d_in[12];
    const float* pfb1 = (const float*)d_in[13];
    const float* pfW2 = (const float*)d_in[14];
    const float* pfb2 = (const float*)d_in[15];
    const float* zkW  = (const float*)d_in[16];
    const float* zkb  = (const float*)d_in[17];
    const float* rkW  = (const float*)d_in[18];
    const float* rkb  = (const float*)d_in[19];
    const float* cW   = (const float*)d_in[20];
    const float* cb   = (const float*)d_in[21];
    const float* eW1  = (const float*)d_in[22];
    const float* eb1  = (const float*)d_in[23];
    const float* eW2  = (const float*)d_in[24];
    const float* eb2  = (const float*)d_in[25];
    const float* dW1  = (const float*)d_in[26];
    const float* db1  = (const float*)d_in[27];
    const float* dW2  = (const float*)d_in[28];
    const float* db2  = (const float*)d_in[29];

    cudaFuncSetAttribute(k_prep, cudaFuncAttributeMaxDynamicSharedMemorySize, PREP_SMEM);
    cudaFuncSetAttribute(k_node, cudaFuncAttributeMaxDynamicSharedMemorySize, NODE_SMEM);

    // device addresses of scratch symbols (host must use cudaGetSymbolAddress)
    int *rowptr, *colptr;
    float4 *rowE4, *colE4;
    float *Pt, *Qt, *Pf, *Qf, *mt, *mf;
    cudaGetSymbolAddress((void**)&rowptr, g_rowptr);
    cudaGetSymbolAddress((void**)&colptr, g_colptr);
    cudaGetSymbolAddress((void**)&rowE4,  g_rowE4);
    cudaGetSymbolAddress((void**)&colE4,  g_colE4);
    cudaGetSymbolAddress((void**)&Pt, g_Pt);
    cudaGetSymbolAddress((void**)&Qt, g_Qt);
    cudaGetSymbolAddress((void**)&Pf, g_Pf);
    cudaGetSymbolAddress((void**)&Qf, g_Qf);
    cudaGetSymbolAddress((void**)&mt, g_mt);
    cudaGetSymbolAddress((void**)&mf, g_mf);

    k_hist<<<(NE+255)/256, 256>>>(ei);                            // 0
    k_scan<<<1, 1024>>>();                                        // 1
    k_scatter<<<(NE+255)/256, 256>>>(ei, ea, aij);                // 2
    k_enc0<<<NB32, 256>>>(x, eW1, eb1, eW2, eb2);                 // 3

    const float gammaw[2] = {0.9f, 1.0f};
    for(int step=0; step<2; step++){
        k_prep<<<2*NB64, 256, PREP_SMEM>>>(ptW1, ptb1, pfW1, pfb1);             // 4 (step0)
        // mess_to: i = col (col-CSR), neighbor j = row
        k_aggr<<<NB32, 256>>>(colptr, colE4, Pt, Qt, ptW1, ptb2, ptW2, mt);     // 5 = profiled
        // mess_from: i = row (row-CSR), neighbor j = col
        k_aggr<<<NB32, 256>>>(rowptr, rowE4, Pf, Qf, pfW1, pfb2, pfW2, mf);
        k_node<<<NB64, 256, NODE_SMEM>>>(tags, prb, zkW, zkb, rkW, rkb, cW, cb,
                                         dW1, db1, dW2, db2, eW1, eb1, eW2, eb2);
        k_res<<<NB32, 256>>>(y, gammaw[step]);
    }
    k_fin<<<(NN+256)/256, 256>>>((float*)d_out, out_size);
}

// round 8
// speedup vs baseline: 1.2070x; 1.1848x over previous
#include <cuda_runtime.h>
#include <math.h>

#define NN 50000
#define NE 800000
#define L  64
#define NB32 ((NN + 31) / 32)
#define NB64 ((NN + 63) / 64)

// ------------- device scratch (statics zero-initialized; k_fin re-zeroes) -------------
__device__ float  g_H [NN*L];
__device__ float  g_H0[NN*L];
__device__ float  g_Pt[NN*L];
__device__ float  g_Qt[NN*L];
__device__ float  g_Pf[NN*L];
__device__ float  g_Qf[NN*L];
__device__ float  g_mt[NN*L];
__device__ float  g_mf[NN*L];
__device__ float  g_U [NN];
__device__ int    g_rowptr[NN+1];
__device__ int    g_colptr[NN+1];
__device__ int    g_cntr[NN];
__device__ int    g_cntc[NN];
__device__ float4 g_rowE4[NE];
__device__ float4 g_colE4[NE];
__device__ float  g_rowA[NE];
__device__ double g_loss;

__device__ __forceinline__ float sigf(float v){ return 1.f/(1.f+__expf(-v)); }

// ---------------- CSR build ----------------
__global__ void k_hist(const int* __restrict__ ei){
    int e = blockIdx.x*blockDim.x + threadIdx.x;
    if(e < NE){
        atomicAdd(&g_cntr[ei[e]], 1);
        atomicAdd(&g_cntc[ei[NE+e]], 1);
    }
}

__device__ void scan_one(int* cnt, int* ptr, int* part){
    const int C = (NN + 1023)/1024;
    int t = threadIdx.x;
    int s = 0;
    for(int k=0;k<C;k++){ int id=t*C+k; if(id<NN) s += cnt[id]; }
    part[t] = s; __syncthreads();
    for(int off=1; off<1024; off<<=1){
        int v = (t>=off)? part[t-off] : 0;
        __syncthreads();
        part[t] += v;
        __syncthreads();
    }
    int run = (t==0)? 0 : part[t-1];
    for(int k=0;k<C;k++){
        int id = t*C+k;
        if(id<NN){ int v=cnt[id]; ptr[id]=run; run+=v; cnt[id]=0; }
    }
    if(t==0) ptr[NN] = part[1023];
    __syncthreads();
}

__global__ void k_scan(){
    __shared__ int part[1024];
    scan_one(g_cntr, g_rowptr, part);
    scan_one(g_cntc, g_colptr, part);
}

__global__ void k_scatter(const int* __restrict__ ei, const float* __restrict__ ea,
                          const float* __restrict__ aij){
    int e = blockIdx.x*blockDim.x + threadIdx.x;
    if(e >= NE) return;
    int r = ei[e], c = ei[NE+e];
    float a0 = ea[3*e], a1 = ea[3*e+1], a2 = ea[3*e+2];
    int pr = atomicAdd(&g_cntr[r], 1);
    int p  = g_rowptr[r] + pr;
    g_rowE4[p] = make_float4(a0,a1,a2,__int_as_float(c));
    g_rowA[p]  = aij[e];
    int pc = atomicAdd(&g_cntc[c], 1);
    int q  = g_colptr[c] + pc;
    g_colE4[q] = make_float4(a0,a1,a2,__int_as_float(r));
}

// ---------------- encoder: x -> H0, H ----------------
__global__ __launch_bounds__(256) void k_enc0(const float* __restrict__ x,
        const float* __restrict__ eW1, const float* __restrict__ eb1,
        const float* __restrict__ eW2, const float* __restrict__ eb2){
    __shared__ float sW[L*L];
    __shared__ float sh[8][4][L];
    int tid = threadIdx.x;
    for(int i=tid;i<L*L/4;i+=256) ((float4*)sW)[i] = ((const float4*)eW2)[i];
    __syncthreads();
    int lane = tid&31, w = tid>>5, c0 = 2*lane;
    int nb = blockIdx.x*32 + w*4;
    float w1a=eW1[c0], w1b=eW1[c0+1], b1a=eb1[c0], b1b=eb1[c0+1];
    float b2a=eb2[c0], b2b=eb2[c0+1];
    bool val[4];
    #pragma unroll
    for(int v=0;v<4;v++){
        int n = nb+v; val[v] = (n<NN);
        float xv = val[v]? x[n] : 0.f;
        sh[w][v][c0]   = fmaxf(fmaf(xv,w1a,b1a),0.f);
        sh[w][v][c0+1] = fmaxf(fmaf(xv,w1b,b1b),0.f);
    }
    __syncwarp();
    float a0[4]={b2a,b2a,b2a,b2a}, a1[4]={b2b,b2b,b2b,b2b};
    for(int k=0;k<L;k++){
        float2 wv = *(const float2*)&sW[k*L+c0];
        #pragma unroll
        for(int v=0;v<4;v++){ float s=sh[w][v][k]; a0[v]=fmaf(s,wv.x,a0[v]); a1[v]=fmaf(s,wv.y,a1[v]); }
    }
    #pragma unroll
    for(int v=0;v<4;v++) if(val[v]){
        int n = nb+v;
        g_H0[n*L+c0]=a0[v]; g_H0[n*L+c0+1]=a1[v];
        g_H [n*L+c0]=a0[v]; g_H [n*L+c0+1]=a1[v];
    }
}

// ---------------- P/Q precompute (both phis), 8 nodes/warp, scalar math ----------------
#define PREP_SMEM ((4*L*L + 64*L)*4)
__global__ __launch_bounds__(256) void k_prep(
        const float* __restrict__ ptW1, const float* __restrict__ ptb1,
        const float* __restrict__ pfW1, const float* __restrict__ pfb1){
    extern __shared__ float sm[];
    float* Wat = sm;            // ptW1 rows 0..63
    float* Wbt = sm + L*L;      // ptW1 rows 64..127
    float* Waf = sm + 2*L*L;
    float* Wbf = sm + 3*L*L;
    float* stg = sm + 4*L*L;    // [64][64] H rows
    int tid = threadIdx.x;
    for(int i=tid;i<L*L/4;i+=256){
        ((float4*)Wat)[i] = ((const float4*)ptW1)[i];
        ((float4*)Wbt)[i] = ((const float4*)(ptW1+L*L))[i];
        ((float4*)Waf)[i] = ((const float4*)pfW1)[i];
        ((float4*)Wbf)[i] = ((const float4*)(pfW1+L*L))[i];
    }
    int lane = tid&31, w = tid>>5, c0 = 2*lane;
    int i0 = w*8, nb = blockIdx.x*64 + i0;
    bool val[8];
    #pragma unroll
    for(int v=0;v<8;v++){
        int n = nb+v; val[v] = (n<NN);
        float2 h = val[v]? *(const float2*)&g_H[n*L+c0] : make_float2(0.f,0.f);
        *(float2*)&stg[(i0+v)*L+c0] = h;
    }
    __syncthreads();
    float pt0[8],pt1[8],qt0[8],qt1[8],pf0[8],pf1[8],qf0[8],qf1[8];
    float bt0=ptb1[c0], bt1=ptb1[c0+1], bf0=pfb1[c0], bf1=pfb1[c0+1];
    #pragma unroll
    for(int v=0;v<8;v++){ pt0[v]=bt0; pt1[v]=bt1; pf0[v]=bf0; pf1[v]=bf1;
                          qt0[v]=0.f; qt1[v]=0.f; qf0[v]=0.f; qf1[v]=0.f; }
    for(int k=0;k<L;k++){
        float2 wat = *(const float2*)&Wat[k*L+c0];
        float2 wbt = *(const float2*)&Wbt[k*L+c0];
        float2 waf = *(const float2*)&Waf[k*L+c0];
        float2 wbf = *(const float2*)&Wbf[k*L+c0];
        #pragma unroll
        for(int v=0;v<8;v++){
            float h = stg[(i0+v)*L + k];
            pt0[v]=fmaf(h,wat.x,pt0[v]); pt1[v]=fmaf(h,wat.y,pt1[v]);
            qt0[v]=fmaf(h,wbt.x,qt0[v]); qt1[v]=fmaf(h,wbt.y,qt1[v]);
            pf0[v]=fmaf(h,waf.x,pf0[v]); pf1[v]=fmaf(h,waf.y,pf1[v]);
            qf0[v]=fmaf(h,wbf.x,qf0[v]); qf1[v]=fmaf(h,wbf.y,qf1[v]);
        }
    }
    #pragma unroll
    for(int v=0;v<8;v++) if(val[v]){
        int n = nb+v;
        g_Pt[n*L+c0]=pt0[v]; g_Pt[n*L+c0+1]=pt1[v];
        g_Qt[n*L+c0]=qt0[v]; g_Qt[n*L+c0+1]=qt1[v];
        g_Pf[n*L+c0]=pf0[v]; g_Pf[n*L+c0+1]=pf1[v];
        g_Qf[n*L+c0]=qf0[v]; g_Qf[n*L+c0+1]=qf1[v];
    }
}

// ---------------- edge aggregation + W2 fold (both directions, one launch) ----------------
__global__ __launch_bounds__(256) void k_aggr(
        const int* __restrict__ colptr, const float4* __restrict__ colE4,
        const int* __restrict__ rowptr, const float4* __restrict__ rowE4,
        const float* __restrict__ Pt, const float* __restrict__ Qt,
        const float* __restrict__ Pf, const float* __restrict__ Qf,
        const float* __restrict__ ptW1, const float* __restrict__ ptb2, const float* __restrict__ ptW2,
        const float* __restrict__ pfW1, const float* __restrict__ pfb2, const float* __restrict__ pfW2,
        float* __restrict__ mt, float* __restrict__ mf){
    __shared__ float sW2[L*L];
    __shared__ float sWe[3*L];
    __shared__ float sS[8][4][L];
    bool toDir = (blockIdx.x < NB32);
    int bb = toDir ? blockIdx.x : blockIdx.x - NB32;
    const int*    ptr = toDir ? colptr : rowptr;
    const float4* e4  = toDir ? colE4  : rowE4;
    const float*  P   = toDir ? Pt     : Pf;
    const float*  Q   = toDir ? Qt     : Qf;
    const float*  W1  = toDir ? ptW1   : pfW1;
    const float*  b2  = toDir ? ptb2   : pfb2;
    const float*  W2  = toDir ? ptW2   : pfW2;
    float*        out = toDir ? mt     : mf;
    int tid = threadIdx.x;
    for(int i=tid;i<L*L/4;i+=256) ((float4*)sW2)[i] = ((const float4*)W2)[i];
    for(int i=tid;i<3*L;i+=256) sWe[i] = W1[2*L*L + i]; // rows 128..130
    __syncthreads();
    int lane = tid&31, w = tid>>5, c0 = 2*lane;
    int nb = bb*32 + w*4;
    float we0a=sWe[c0],     we0b=sWe[c0+1];
    float we1a=sWe[L+c0],   we1b=sWe[L+c0+1];
    float we2a=sWe[2*L+c0], we2b=sWe[2*L+c0+1];
    float degv[4]; bool val[4];
    #pragma unroll
    for(int v=0;v<4;v++){
        int n = nb+v; val[v] = (n<NN);
        float acc0=0.f, acc1=0.f; int cnt=0;
        if(val[v]){
            float base0 = P[n*L+c0], base1 = P[n*L+c0+1];
            int s = ptr[n], e = ptr[n+1];
            for(int p=s; p<e; p++){
                float4 E = e4[p];
                int j = __float_as_int(E.w);
                if(j == n) continue;
                cnt++;
                float2 qv = *(const float2*)&Q[j*L+c0];
                float pre0 = base0 + qv.x + E.x*we0a + E.y*we1a + E.z*we2a;
                float pre1 = base1 + qv.y + E.x*we0b + E.y*we1b + E.z*we2b;
                acc0 += fmaxf(pre0, 0.f);
                acc1 += fmaxf(pre1, 0.f);
            }
        }
        sS[w][v][c0]=acc0; sS[w][v][c0+1]=acc1; degv[v]=(float)cnt;
    }
    __syncwarp();
    float b2a=b2[c0], b2b=b2[c0+1];
    float o0[4],o1[4];
    #pragma unroll
    for(int v=0;v<4;v++){ o0[v]=degv[v]*b2a; o1[v]=degv[v]*b2b; }
    for(int k=0;k<L;k++){
        float2 wv = *(const float2*)&sW2[k*L+c0];
        #pragma unroll
        for(int v=0;v<4;v++){ float s=sS[w][v][k]; o0[v]=fmaf(s,wv.x,o0[v]); o1[v]=fmaf(s,wv.y,o1[v]); }
    }
    #pragma unroll
    for(int v=0;v<4;v++) if(val[v]){
        int n = nb+v;
        out[n*L+c0]=o0[v]; out[n*L+c0+1]=o1[v];
    }
}

// ---------------- fused node update: 64 nodes/block, 8 nodes/warp, scalar math ----------------
#define NODE_SMEM ((3*194*L + 64*196 + 64*L)*4)
__global__ __launch_bounds__(256) void k_node(
        const int* __restrict__ tags, const float* __restrict__ prb,
        const float* __restrict__ zkW, const float* __restrict__ zkb,
        const float* __restrict__ rkW, const float* __restrict__ rkb,
        const float* __restrict__ cW,  const float* __restrict__ cb,
        const float* __restrict__ dW1, const float* __restrict__ db1,
        const float* __restrict__ dW2, const float* __restrict__ db2,
        const float* __restrict__ eW1, const float* __restrict__ eb1,
        const float* __restrict__ eW2, const float* __restrict__ eb2){
    extern __shared__ float sm[];
    float* szk  = sm;                 // 194*64
    float* srk  = szk + 194*L;
    float* scw  = srk + 194*L;
    float* stgA = scw + 194*L;        // [64][196]
    float* stgB = stgA + 64*196;      // [64][64]
    __shared__ float sdW2[L], sdb1[L], sE1[L], sEb1[L], szb[L], srb[L], scb[L], sEb2[L];
    __shared__ double red[8];
    int tid = threadIdx.x;
    for(int i=tid;i<194*L/4;i+=256){
        ((float4*)szk)[i] = ((const float4*)zkW)[i];
        ((float4*)srk)[i] = ((const float4*)rkW)[i];
        ((float4*)scw)[i] = ((const float4*)cW)[i];
    }
    if(tid<L){ sdW2[tid]=dW2[tid]; sdb1[tid]=db1[tid]; sE1[tid]=eW1[tid]; sEb1[tid]=eb1[tid];
               szb[tid]=zkb[tid]; srb[tid]=rkb[tid]; scb[tid]=cb[tid]; sEb2[tid]=eb2[tid]; }
    int lane = tid&31, w = tid>>5, c0 = 2*lane;
    int i0 = w*8, nb = blockIdx.x*64 + i0;
    float db2v = db2[0];
    bool val[8];
    // stage cat = [H, mt, mf, prb]
    #pragma unroll
    for(int v=0;v<8;v++){
        int n = nb+v; val[v] = (n<NN);
        float* A = stgA + (i0+v)*196;
        if(val[v]){
            *(float2*)&A[c0]     = *(const float2*)&g_H [n*L+c0];
            *(float2*)&A[64+c0]  = *(const float2*)&g_mt[n*L+c0];
            *(float2*)&A[128+c0] = *(const float2*)&g_mf[n*L+c0];
            if(lane==0){ A[192]=prb[2*n]; A[193]=prb[2*n+1]; }
        } else {
            *(float2*)&A[c0]     = make_float2(0.f,0.f);
            *(float2*)&A[64+c0]  = make_float2(0.f,0.f);
            *(float2*)&A[128+c0] = make_float2(0.f,0.f);
            if(lane==0){ A[192]=0.f; A[193]=0.f; }
        }
    }
    __syncthreads();
    float az0[8],az1[8],ar0[8],ar1[8],ac0[8],ac1[8];
    #pragma unroll
    for(int v=0;v<8;v++){ az0[v]=0.f; az1[v]=0.f; ar0[v]=0.f; ar1[v]=0.f; ac0[v]=0.f; ac1[v]=0.f; }
    for(int k=0;k<64;k++){
        float2 wz = *(const float2*)&szk[k*L+c0];
        float2 wr = *(const float2*)&srk[k*L+c0];
        #pragma unroll
        for(int v=0;v<8;v++){
            float cv = stgA[(i0+v)*196 + k];
            az0[v]=fmaf(cv,wz.x,az0[v]); az1[v]=fmaf(cv,wz.y,az1[v]);
            ar0[v]=fmaf(cv,wr.x,ar0[v]); ar1[v]=fmaf(cv,wr.y,ar1[v]);
        }
    }
    for(int k=64;k<194;k++){
        float2 wz = *(const float2*)&szk[k*L+c0];
        float2 wr = *(const float2*)&srk[k*L+c0];
        float2 wc = *(const float2*)&scw[k*L+c0];
        #pragma unroll
        for(int v=0;v<8;v++){
            float cv = stgA[(i0+v)*196 + k];
            az0[v]=fmaf(cv,wz.x,az0[v]); az1[v]=fmaf(cv,wz.y,az1[v]);
            ar0[v]=fmaf(cv,wr.x,ar0[v]); ar1[v]=fmaf(cv,wr.y,ar1[v]);
            ac0[v]=fmaf(cv,wc.x,ac0[v]); ac1[v]=fmaf(cv,wc.y,ac1[v]);
        }
    }
    // activations: z, r (r -> stgB)
    float z0[8],z1[8];
    #pragma unroll
    for(int v=0;v<8;v++){
        z0[v]=sigf(az0[v]+szb[c0]); z1[v]=sigf(az1[v]+szb[c0+1]);
        float rr0=sigf(ar0[v]+srb[c0]), rr1=sigf(ar1[v]+srb[c0+1]);
        stgB[(i0+v)*L+c0]=rr0; stgB[(i0+v)*L+c0+1]=rr1;
    }
    __syncwarp();
    // corr reset part (k<64)
    for(int k=0;k<64;k++){
        float2 wc = *(const float2*)&scw[k*L+c0];
        #pragma unroll
        for(int v=0;v<8;v++){
            float rh = stgB[(i0+v)*L+k] * stgA[(i0+v)*196+k];
            ac0[v]=fmaf(rh,wc.x,ac0[v]); ac1[v]=fmaf(rh,wc.y,ac1[v]);
        }
    }
    // Hn, write back, restage
    float Hn0[8], Hn1[8];
    #pragma unroll
    for(int v=0;v<8;v++){
        int n = nb+v;
        float* A = stgA + (i0+v)*196;
        float co0 = tanhf(ac0[v]+scb[c0]);
        float co1 = tanhf(ac1[v]+scb[c0+1]);
        float h0 = A[c0], h1 = A[c0+1];
        float hn0 = h0 + z0[v]*co0, hn1 = h1 + z1[v]*co1;
        if(val[v] && tags[n]==1){ hn0 = g_H0[n*L+c0]; hn1 = g_H0[n*L+c0+1]; }
        Hn0[v]=hn0; Hn1[v]=hn1;
        A[c0]=hn0; A[c0+1]=hn1;
        if(val[v]){ g_H[n*L+c0]=hn0; g_H[n*L+c0+1]=hn1; }
    }
    __syncwarp();
    // decoder: U = relu(Hn@dW1+db1)@dW2 + db2  (dW1 via LDG, L1-resident)
    float ad0[8],ad1[8];
    #pragma unroll
    for(int v=0;v<8;v++){ ad0[v]=sdb1[c0]; ad1[v]=sdb1[c0+1]; }
    for(int k=0;k<L;k++){
        float2 wd = __ldg((const float2*)&dW1[k*L+c0]);
        #pragma unroll
        for(int v=0;v<8;v++){
            float hk = stgA[(i0+v)*196 + k];
            ad0[v]=fmaf(hk,wd.x,ad0[v]); ad1[v]=fmaf(hk,wd.y,ad1[v]);
        }
    }
    float Uv[8];
    #pragma unroll
    for(int v=0;v<8;v++){
        float pu = fmaxf(ad0[v],0.f)*sdW2[c0] + fmaxf(ad1[v],0.f)*sdW2[c0+1];
        for(int o=16;o;o>>=1) pu += __shfl_xor_sync(0xffffffffu, pu, o);
        Uv[v] = pu + db2v;
        int n = nb+v;
        if(val[v] && lane==0) g_U[n] = Uv[v];
        float eh0 = fmaxf(fmaf(Uv[v],sE1[c0],sEb1[c0]),0.f);
        float eh1 = fmaxf(fmaf(Uv[v],sE1[c0+1],sEb1[c0+1]),0.f);
        stgB[(i0+v)*L+c0]=eh0; stgB[(i0+v)*L+c0+1]=eh1;
    }
    __syncwarp();
    // enc(U): 64x64 GEMV (eW2 via LDG)
    float ae0[8],ae1[8];
    #pragma unroll
    for(int v=0;v<8;v++){ ae0[v]=sEb2[c0]; ae1[v]=sEb2[c0+1]; }
    for(int k=0;k<L;k++){
        float2 we = __ldg((const float2*)&eW2[k*L+c0]);
        #pragma unroll
        for(int v=0;v<8;v++){
            float ek = stgB[(i0+v)*L+k];
            ae0[v]=fmaf(ek,we.x,ae0[v]); ae1[v]=fmaf(ek,we.y,ae1[v]);
        }
    }
    float encS = 0.f;
    #pragma unroll
    for(int v=0;v<8;v++){
        float* A = stgA + (i0+v)*196;
        if(val[v]){
            float d0 = ae0[v]-Hn0[v], d1 = ae1[v]-Hn1[v];
            encS += d0*d0 + d1*d1;
        }
        A[64+c0]=ae0[v]; A[64+c0+1]=ae1[v];   // stash enc for autoenc pass
    }
    __syncwarp();
    // autoenc: dec(enc)
    float ag0[8],ag1[8];
    #pragma unroll
    for(int v=0;v<8;v++){ ag0[v]=sdb1[c0]; ag1[v]=sdb1[c0+1]; }
    for(int k=0;k<L;k++){
        float2 wd = __ldg((const float2*)&dW1[k*L+c0]);
        #pragma unroll
        for(int v=0;v<8;v++){
            float ek = stgA[(i0+v)*196 + 64 + k];
            ag0[v]=fmaf(ek,wd.x,ag0[v]); ag1[v]=fmaf(ek,wd.y,ag1[v]);
        }
    }
    float autoS = 0.f;
    #pragma unroll
    for(int v=0;v<8;v++){
        float pa = fmaxf(ag0[v],0.f)*sdW2[c0] + fmaxf(ag1[v],0.f)*sdW2[c0+1];
        for(int o=16;o;o>>=1) pa += __shfl_xor_sync(0xffffffffu, pa, o);
        float aout = pa + db2v;
        if(val[v] && lane==0){ float d = aout - Uv[v]; autoS += d*d; }
    }
    // loss reduction: enc_loss/(N*64) + autoenc_loss/N
    float tot = encS;
    for(int o=16;o;o>>=1) tot += __shfl_xor_sync(0xffffffffu, tot, o);
    float at = autoS;
    for(int o=16;o;o>>=1) at += __shfl_xor_sync(0xffffffffu, at, o);
    if(lane==0) red[w] = (double)tot/((double)NN*64.0) + (double)at/(double)NN;
    __syncthreads();
    if(tid==0){
        double s = 0.0;
        for(int i=0;i<8;i++) s += red[i];
        atomicAdd(&g_loss, s);
    }
}

// ---------------- residual loss ----------------
__global__ __launch_bounds__(256) void k_res(const float* __restrict__ y, float wgt){
    __shared__ double red[8];
    int lane = threadIdx.x&31, w = threadIdx.x>>5;
    int wid = blockIdx.x*8 + w;
    int nwarps = gridDim.x*8;
    float ls = 0.f;
    for(int n = wid; n < NN; n += nwarps){
        int s = g_rowptr[n], e = g_rowptr[n+1];
        float part = 0.f;
        for(int p = s+lane; p < e; p += 32){
            int j = __float_as_int(g_rowE4[p].w);
            part += g_rowA[p] * g_U[j];
        }
        for(int o=16;o;o>>=1) part += __shfl_xor_sync(0xffffffffu, part, o);
        if(lane==0){ float d = part - y[n]; ls += d*d; }
    }
    for(int o=16;o;o>>=1) ls += __shfl_xor_sync(0xffffffffu, ls, o);
    if(lane==0) red[w] = (double)ls;
    __syncthreads();
    if(threadIdx.x==0){
        double s=0.0; for(int i=0;i<8;i++) s+=red[i];
        atomicAdd(&g_loss, s * (double)wgt / (double)NN);
    }
}

// ---------------- finalize + reset state for next replay ----------------
__global__ void k_fin(float* __restrict__ out, int out_size){
    int i = blockIdx.x*blockDim.x + threadIdx.x;
    if(i < NN && i < out_size) out[i] = g_U[i];
    if(i == NN){
        if(i < out_size) out[NN] = (float)g_loss;
        g_loss = 0.0;
    }
    if(i < NN){ g_cntr[i]=0; g_cntc[i]=0; }
}

extern "C" void kernel_launch(void* const* d_in, const int* in_sizes, int n_in,
                              void* d_out, int out_size){
    const float* x    = (const float*)d_in[0];
    const float* y    = (const float*)d_in[2];
    const int*   tags = (const int*)  d_in[3];
    const int*   ei   = (const int*)  d_in[4];
    const float* ea   = (const float*)d_in[5];
    const float* aij  = (const float*)d_in[6];
    const float* prb  = (const float*)d_in[7];
    const float* ptW1 = (const float*)d_in[8];
    const float* ptb1 = (const float*)d_in[9];
    const float* ptW2 = (const float*)d_in[10];
    const float* ptb2 = (const float*)d_in[11];
    const float* pfW1 = (const float*)d_in[12];
    const float* pfb1 = (const float*)d_in[13];
    const float* pfW2 = (const float*)d_in[14];
    const float* pfb2 = (const float*)d_in[15];
    const float* zkW  = (const float*)d_in[16];
    const float* zkb  = (const float*)d_in[17];
    const float* rkW  = (const float*)d_in[18];
    const float* rkb  = (const float*)d_in[19];
    const float* cW   = (const float*)d_in[20];
    const float* cb   = (const float*)d_in[21];
    const float* eW1  = (const float*)d_in[22];
    const float* eb1  = (const float*)d_in[23];
    const float* eW2  = (const float*)d_in[24];
    const float* eb2  = (const float*)d_in[25];
    const float* dW1  = (const float*)d_in[26];
    const float* db1  = (const float*)d_in[27];
    const float* dW2  = (const float*)d_in[28];
    const float* db2  = (const float*)d_in[29];

    cudaFuncSetAttribute(k_prep, cudaFuncAttributeMaxDynamicSharedMemorySize, PREP_SMEM);
    cudaFuncSetAttribute(k_node, cudaFuncAttributeMaxDynamicSharedMemorySize, NODE_SMEM);

    // device addresses of scratch symbols (host must use cudaGetSymbolAddress)
    int *rowptr, *colptr;
    float4 *rowE4, *colE4;
    float *Pt, *Qt, *Pf, *Qf, *mt, *mf;
    cudaGetSymbolAddress((void**)&rowptr, g_rowptr);
    cudaGetSymbolAddress((void**)&colptr, g_colptr);
    cudaGetSymbolAddress((void**)&rowE4,  g_rowE4);
    cudaGetSymbolAddress((void**)&colE4,  g_colE4);
    cudaGetSymbolAddress((void**)&Pt, g_Pt);
    cudaGetSymbolAddress((void**)&Qt, g_Qt);
    cudaGetSymbolAddress((void**)&Pf, g_Pf);
    cudaGetSymbolAddress((void**)&Qf, g_Qf);
    cudaGetSymbolAddress((void**)&mt, g_mt);
    cudaGetSymbolAddress((void**)&mf, g_mf);

    k_enc0<<<NB32, 256>>>(x, eW1, eb1, eW2, eb2);                     // 0
    k_hist<<<(NE+255)/256, 256>>>(ei);                                // 1
    k_scan<<<1, 1024>>>();                                            // 2
    k_prep<<<NB64, 256, PREP_SMEM>>>(ptW1, ptb1, pfW1, pfb1);         // 3 (profiled slot)
    k_scatter<<<(NE+255)/256, 256>>>(ei, ea, aij);                    // 4

    const float gammaw[2] = {0.9f, 1.0f};
    for(int step=0; step<2; step++){
        if(step > 0)
            k_prep<<<NB64, 256, PREP_SMEM>>>(ptW1, ptb1, pfW1, pfb1);
        k_aggr<<<2*NB32, 256>>>(colptr, colE4, rowptr, rowE4,
                                Pt, Qt, Pf, Qf,
                                ptW1, ptb2, ptW2, pfW1, pfb2, pfW2, mt, mf);
        k_node<<<NB64, 256, NODE_SMEM>>>(tags, prb, zkW, zkb, rkW, rkb, cW, cb,
                                         dW1, db1, dW2, db2, eW1, eb1, eW2, eb2);
        k_res<<<NB32, 256>>>(y, gammaw[step]);
    }
    k_fin<<<(NN+256)/256, 256>>>((float*)d_out, out_size);
}

// round 9
// speedup vs baseline: 1.6075x; 1.3319x over previous
#include <cuda_runtime.h>
#include <math.h>

#define NN 50000
#define NE 800000
#define L  64
#define NB32 ((NN + 31) / 32)
#define NB64 ((NN + 63) / 64)

// ------------- device scratch (statics zero-initialized; k_fin re-zeroes) -------------
__device__ float  g_H [NN*L];
__device__ float  g_H0[NN*L];
__device__ float  g_Pt[NN*L];
__device__ float  g_Qt[NN*L];
__device__ float  g_Pf[NN*L];
__device__ float  g_Qf[NN*L];
__device__ float  g_mt[NN*L];
__device__ float  g_mf[NN*L];
__device__ float  g_U [NN];
__device__ int    g_rowptr[NN+1];
__device__ int    g_colptr[NN+1];
__device__ int    g_cntr[NN];
__device__ int    g_cntc[NN];
__device__ int    g_nd[NN];      // non-Dirichlet node ids
__device__ int    g_dr[NN];      // Dirichlet node ids
__device__ int    g_ndcount;
__device__ int    g_drcount;
__device__ float4 g_rowE4[NE];
__device__ float4 g_colE4[NE];
__device__ float  g_rowA[NE];
__device__ double g_loss;

__device__ __forceinline__ float sigf(float v){ return 1.f/(1.f+__expf(-v)); }

// ---------------- CSR build ----------------
__global__ void k_hist(const int* __restrict__ ei){
    int e = blockIdx.x*blockDim.x + threadIdx.x;
    if(e < NE){
        atomicAdd(&g_cntr[ei[e]], 1);
        atomicAdd(&g_cntc[ei[NE+e]], 1);
    }
}

__device__ void scan_one(int* cnt, int* ptr, int* part){
    const int C = (NN + 1023)/1024;
    int t = threadIdx.x;
    int s = 0;
    for(int k=0;k<C;k++){ int id=t*C+k; if(id<NN) s += cnt[id]; }
    part[t] = s; __syncthreads();
    for(int off=1; off<1024; off<<=1){
        int v = (t>=off)? part[t-off] : 0;
        __syncthreads();
        part[t] += v;
        __syncthreads();
    }
    int run = (t==0)? 0 : part[t-1];
    for(int k=0;k<C;k++){
        int id = t*C+k;
        if(id<NN){ int v=cnt[id]; ptr[id]=run; run+=v; cnt[id]=0; }
    }
    if(t==0) ptr[NN] = part[1023];
    __syncthreads();
}

__global__ void k_scan(const int* __restrict__ tags){
    __shared__ int part[1024];
    scan_one(g_cntr, g_rowptr, part);
    scan_one(g_cntc, g_colptr, part);
    // deterministic compaction of non-dir / dir node lists
    const int C = (NN + 1023)/1024;
    int t = threadIdx.x;
    int cN = 0;
    for(int k=0;k<C;k++){ int id=t*C+k; if(id<NN && tags[id]!=1) cN++; }
    part[t] = cN; __syncthreads();
    for(int off=1; off<1024; off<<=1){
        int v = (t>=off)? part[t-off] : 0;
        __syncthreads();
        part[t] += v;
        __syncthreads();
    }
    int ndBase = (t==0)? 0 : part[t-1];
    int idsBefore = t*C; if(idsBefore > NN) idsBefore = NN;
    int drBase = idsBefore - ndBase;
    for(int k=0;k<C;k++){
        int id = t*C+k;
        if(id<NN){
            if(tags[id]!=1) g_nd[ndBase++] = id;
            else            g_dr[drBase++] = id;
        }
    }
    if(t==1023){ g_ndcount = part[1023]; g_drcount = NN - part[1023]; }
}

__global__ void k_scatter(const int* __restrict__ ei, const float* __restrict__ ea,
                          const float* __restrict__ aij){
    int e = blockIdx.x*blockDim.x + threadIdx.x;
    if(e >= NE) return;
    int r = ei[e], c = ei[NE+e];
    float a0 = ea[3*e], a1 = ea[3*e+1], a2 = ea[3*e+2];
    int pr = atomicAdd(&g_cntr[r], 1);
    int p  = g_rowptr[r] + pr;
    g_rowE4[p] = make_float4(a0,a1,a2,__int_as_float(c));
    g_rowA[p]  = aij[e];
    int pc = atomicAdd(&g_cntc[c], 1);
    int q  = g_colptr[c] + pc;
    g_colE4[q] = make_float4(a0,a1,a2,__int_as_float(r));
}

// ---------------- encoder: x -> H0, H ----------------
__global__ __launch_bounds__(256) void k_enc0(const float* __restrict__ x,
        const float* __restrict__ eW1, const float* __restrict__ eb1,
        const float* __restrict__ eW2, const float* __restrict__ eb2){
    __shared__ float sW[L*L];
    __shared__ float sh[8][4][L];
    int tid = threadIdx.x;
    for(int i=tid;i<L*L/4;i+=256) ((float4*)sW)[i] = ((const float4*)eW2)[i];
    __syncthreads();
    int lane = tid&31, w = tid>>5, c0 = 2*lane;
    int nb = blockIdx.x*32 + w*4;
    float w1a=eW1[c0], w1b=eW1[c0+1], b1a=eb1[c0], b1b=eb1[c0+1];
    float b2a=eb2[c0], b2b=eb2[c0+1];
    bool val[4];
    #pragma unroll
    for(int v=0;v<4;v++){
        int n = nb+v; val[v] = (n<NN);
        float xv = val[v]? x[n] : 0.f;
        sh[w][v][c0]   = fmaxf(fmaf(xv,w1a,b1a),0.f);
        sh[w][v][c0+1] = fmaxf(fmaf(xv,w1b,b1b),0.f);
    }
    __syncwarp();
    float a0[4]={b2a,b2a,b2a,b2a}, a1[4]={b2b,b2b,b2b,b2b};
    for(int k=0;k<L;k++){
        float2 wv = *(const float2*)&sW[k*L+c0];
        #pragma unroll
        for(int v=0;v<4;v++){ float s=sh[w][v][k]; a0[v]=fmaf(s,wv.x,a0[v]); a1[v]=fmaf(s,wv.y,a1[v]); }
    }
    #pragma unroll
    for(int v=0;v<4;v++) if(val[v]){
        int n = nb+v;
        g_H0[n*L+c0]=a0[v]; g_H0[n*L+c0+1]=a1[v];
        g_H [n*L+c0]=a0[v]; g_H [n*L+c0+1]=a1[v];
    }
}

// ---------------- P/Q precompute (both phis), 8 nodes/warp, optional nd-perm ----------------
#define PREP_SMEM ((4*L*L + 64*L)*4)
__global__ __launch_bounds__(256) void k_prep(
        const float* __restrict__ ptW1, const float* __restrict__ ptb1,
        const float* __restrict__ pfW1, const float* __restrict__ pfb1,
        int use_perm){
    if(use_perm && blockIdx.x*64 >= g_ndcount) return;
    extern __shared__ float sm[];
    float* Wat = sm;            // ptW1 rows 0..63
    float* Wbt = sm + L*L;      // ptW1 rows 64..127
    float* Waf = sm + 2*L*L;
    float* Wbf = sm + 3*L*L;
    float* stg = sm + 4*L*L;    // [64][64] H rows
    int tid = threadIdx.x;
    for(int i=tid;i<L*L/4;i+=256){
        ((float4*)Wat)[i] = ((const float4*)ptW1)[i];
        ((float4*)Wbt)[i] = ((const float4*)(ptW1+L*L))[i];
        ((float4*)Waf)[i] = ((const float4*)pfW1)[i];
        ((float4*)Wbf)[i] = ((const float4*)(pfW1+L*L))[i];
    }
    int lane = tid&31, w = tid>>5, c0 = 2*lane;
    int i0 = w*8, sb = blockIdx.x*64 + i0;
    int nid[8]; bool val[8];
    #pragma unroll
    for(int v=0;v<8;v++){
        int slot = sb+v;
        if(use_perm){ val[v] = (slot < g_ndcount); nid[v] = val[v]? g_nd[slot] : 0; }
        else        { val[v] = (slot < NN);        nid[v] = slot; }
        float2 h = val[v]? *(const float2*)&g_H[nid[v]*L+c0] : make_float2(0.f,0.f);
        *(float2*)&stg[(i0+v)*L+c0] = h;
    }
    __syncthreads();
    float pt0[8],pt1[8],qt0[8],qt1[8],pf0[8],pf1[8],qf0[8],qf1[8];
    float bt0=ptb1[c0], bt1=ptb1[c0+1], bf0=pfb1[c0], bf1=pfb1[c0+1];
    #pragma unroll
    for(int v=0;v<8;v++){ pt0[v]=bt0; pt1[v]=bt1; pf0[v]=bf0; pf1[v]=bf1;
                          qt0[v]=0.f; qt1[v]=0.f; qf0[v]=0.f; qf1[v]=0.f; }
    for(int k=0;k<L;k++){
        float2 wat = *(const float2*)&Wat[k*L+c0];
        float2 wbt = *(const float2*)&Wbt[k*L+c0];
        float2 waf = *(const float2*)&Waf[k*L+c0];
        float2 wbf = *(const float2*)&Wbf[k*L+c0];
        #pragma unroll
        for(int v=0;v<8;v++){
            float h = stg[(i0+v)*L + k];
            pt0[v]=fmaf(h,wat.x,pt0[v]); pt1[v]=fmaf(h,wat.y,pt1[v]);
            qt0[v]=fmaf(h,wbt.x,qt0[v]); qt1[v]=fmaf(h,wbt.y,qt1[v]);
            pf0[v]=fmaf(h,waf.x,pf0[v]); pf1[v]=fmaf(h,waf.y,pf1[v]);
            qf0[v]=fmaf(h,wbf.x,qf0[v]); qf1[v]=fmaf(h,wbf.y,qf1[v]);
        }
    }
    #pragma unroll
    for(int v=0;v<8;v++) if(val[v]){
        int n = nid[v];
        g_Pt[n*L+c0]=pt0[v]; g_Pt[n*L+c0+1]=pt1[v];
        g_Qt[n*L+c0]=qt0[v]; g_Qt[n*L+c0+1]=qt1[v];
        g_Pf[n*L+c0]=pf0[v]; g_Pf[n*L+c0+1]=pf1[v];
        g_Qf[n*L+c0]=qf0[v]; g_Qf[n*L+c0+1]=qf1[v];
    }
}

// ---------------- edge aggregation + W2 fold (non-dir targets only) ----------------
__global__ __launch_bounds__(256) void k_aggr(
        const int* __restrict__ colptr, const float4* __restrict__ colE4,
        const int* __restrict__ rowptr, const float4* __restrict__ rowE4,
        const float* __restrict__ Pt, const float* __restrict__ Qt,
        const float* __restrict__ Pf, const float* __restrict__ Qf,
        const float* __restrict__ ptW1, const float* __restrict__ ptb2, const float* __restrict__ ptW2,
        const float* __restrict__ pfW1, const float* __restrict__ pfb2, const float* __restrict__ pfW2,
        float* __restrict__ mt, float* __restrict__ mf){
    bool toDir = (blockIdx.x < NB32);
    int bb = toDir ? blockIdx.x : blockIdx.x - NB32;
    if(bb*32 >= g_ndcount) return;
    __shared__ float sW2[L*L];
    __shared__ float sWe[3*L];
    __shared__ float sS[8][4][L];
    const int*    ptr = toDir ? colptr : rowptr;
    const float4* e4  = toDir ? colE4  : rowE4;
    const float*  P   = toDir ? Pt     : Pf;
    const float*  Q   = toDir ? Qt     : Qf;
    const float*  W1  = toDir ? ptW1   : pfW1;
    const float*  b2  = toDir ? ptb2   : pfb2;
    const float*  W2  = toDir ? ptW2   : pfW2;
    float*        out = toDir ? mt     : mf;
    int tid = threadIdx.x;
    for(int i=tid;i<L*L/4;i+=256) ((float4*)sW2)[i] = ((const float4*)W2)[i];
    for(int i=tid;i<3*L;i+=256) sWe[i] = W1[2*L*L + i]; // rows 128..130
    __syncthreads();
    int lane = tid&31, w = tid>>5, c0 = 2*lane;
    int sb = bb*32 + w*4;
    float we0a=sWe[c0],     we0b=sWe[c0+1];
    float we1a=sWe[L+c0],   we1b=sWe[L+c0+1];
    float we2a=sWe[2*L+c0], we2b=sWe[2*L+c0+1];
    float degv[4]; bool val[4]; int nid[4];
    #pragma unroll
    for(int v=0;v<4;v++){
        int slot = sb+v;
        val[v] = (slot < g_ndcount);
        int n = val[v]? g_nd[slot] : 0;
        nid[v] = n;
        float acc0=0.f, acc1=0.f; int cnt=0;
        if(val[v]){
            float base0 = P[n*L+c0], base1 = P[n*L+c0+1];
            int s = ptr[n], e = ptr[n+1];
            for(int p=s; p<e; p++){
                float4 E = e4[p];
                int j = __float_as_int(E.w);
                if(j == n) continue;
                cnt++;
                float2 qv = *(const float2*)&Q[j*L+c0];
                float pre0 = base0 + qv.x + E.x*we0a + E.y*we1a + E.z*we2a;
                float pre1 = base1 + qv.y + E.x*we0b + E.y*we1b + E.z*we2b;
                acc0 += fmaxf(pre0, 0.f);
                acc1 += fmaxf(pre1, 0.f);
            }
        }
        sS[w][v][c0]=acc0; sS[w][v][c0+1]=acc1; degv[v]=(float)cnt;
    }
    __syncwarp();
    float b2a=b2[c0], b2b=b2[c0+1];
    float o0[4],o1[4];
    #pragma unroll
    for(int v=0;v<4;v++){ o0[v]=degv[v]*b2a; o1[v]=degv[v]*b2b; }
    for(int k=0;k<L;k++){
        float2 wv = *(const float2*)&sW2[k*L+c0];
        #pragma unroll
        for(int v=0;v<4;v++){ float s=sS[w][v][k]; o0[v]=fmaf(s,wv.x,o0[v]); o1[v]=fmaf(s,wv.y,o1[v]); }
    }
    #pragma unroll
    for(int v=0;v<4;v++) if(val[v]){
        int n = nid[v];
        out[n*L+c0]=o0[v]; out[n*L+c0+1]=o1[v];
    }
}

// ---------------- gates: non-dir nodes only, 64/block, 8/warp ----------------
#define GATE_SMEM ((3*194*L + 64*196 + 64*L)*4)
__global__ __launch_bounds__(256) void k_gate(
        const float* __restrict__ prb,
        const float* __restrict__ zkW, const float* __restrict__ zkb,
        const float* __restrict__ rkW, const float* __restrict__ rkb,
        const float* __restrict__ cW,  const float* __restrict__ cb){
    if(blockIdx.x*64 >= g_ndcount) return;
    extern __shared__ float sm[];
    float* szk  = sm;                 // 194*64
    float* srk  = szk + 194*L;
    float* scw  = srk + 194*L;
    float* stgA = scw + 194*L;        // [64][196]
    float* stgB = stgA + 64*196;      // [64][64]
    __shared__ float szb[L], srb[L], scb[L];
    int tid = threadIdx.x;
    for(int i=tid;i<194*L/4;i+=256){
        ((float4*)szk)[i] = ((const float4*)zkW)[i];
        ((float4*)srk)[i] = ((const float4*)rkW)[i];
        ((float4*)scw)[i] = ((const float4*)cW)[i];
    }
    if(tid<L){ szb[tid]=zkb[tid]; srb[tid]=rkb[tid]; scb[tid]=cb[tid]; }
    int lane = tid&31, w = tid>>5, c0 = 2*lane;
    int i0 = w*8, sb = blockIdx.x*64 + i0;
    int nid[8]; bool val[8];
    #pragma unroll
    for(int v=0;v<8;v++){
        int slot = sb+v; val[v] = (slot < g_ndcount);
        int n = val[v]? g_nd[slot] : 0; nid[v] = n;
        float* A = stgA + (i0+v)*196;
        if(val[v]){
            *(float2*)&A[c0]     = *(const float2*)&g_H [n*L+c0];
            *(float2*)&A[64+c0]  = *(const float2*)&g_mt[n*L+c0];
            *(float2*)&A[128+c0] = *(const float2*)&g_mf[n*L+c0];
            if(lane==0){ A[192]=prb[2*n]; A[193]=prb[2*n+1]; }
        } else {
            *(float2*)&A[c0]     = make_float2(0.f,0.f);
            *(float2*)&A[64+c0]  = make_float2(0.f,0.f);
            *(float2*)&A[128+c0] = make_float2(0.f,0.f);
            if(lane==0){ A[192]=0.f; A[193]=0.f; }
        }
    }
    __syncthreads();
    float az0[8],az1[8],ar0[8],ar1[8],ac0[8],ac1[8];
    #pragma unroll
    for(int v=0;v<8;v++){ az0[v]=0.f; az1[v]=0.f; ar0[v]=0.f; ar1[v]=0.f; ac0[v]=0.f; ac1[v]=0.f; }
    for(int k=0;k<64;k++){
        float2 wz = *(const float2*)&szk[k*L+c0];
        float2 wr = *(const float2*)&srk[k*L+c0];
        #pragma unroll
        for(int v=0;v<8;v++){
            float cv = stgA[(i0+v)*196 + k];
            az0[v]=fmaf(cv,wz.x,az0[v]); az1[v]=fmaf(cv,wz.y,az1[v]);
            ar0[v]=fmaf(cv,wr.x,ar0[v]); ar1[v]=fmaf(cv,wr.y,ar1[v]);
        }
    }
    for(int k=64;k<194;k++){
        float2 wz = *(const float2*)&szk[k*L+c0];
        float2 wr = *(const float2*)&srk[k*L+c0];
        float2 wc = *(const float2*)&scw[k*L+c0];
        #pragma unroll
        for(int v=0;v<8;v++){
            float cv = stgA[(i0+v)*196 + k];
            az0[v]=fmaf(cv,wz.x,az0[v]); az1[v]=fmaf(cv,wz.y,az1[v]);
            ar0[v]=fmaf(cv,wr.x,ar0[v]); ar1[v]=fmaf(cv,wr.y,ar1[v]);
            ac0[v]=fmaf(cv,wc.x,ac0[v]); ac1[v]=fmaf(cv,wc.y,ac1[v]);
        }
    }
    float z0[8],z1[8];
    #pragma unroll
    for(int v=0;v<8;v++){
        z0[v]=sigf(az0[v]+szb[c0]); z1[v]=sigf(az1[v]+szb[c0+1]);
        float rr0=sigf(ar0[v]+srb[c0]), rr1=sigf(ar1[v]+srb[c0+1]);
        stgB[(i0+v)*L+c0]=rr0; stgB[(i0+v)*L+c0+1]=rr1;
    }
    __syncwarp();
    for(int k=0;k<64;k++){
        float2 wc = *(const float2*)&scw[k*L+c0];
        #pragma unroll
        for(int v=0;v<8;v++){
            float rh = stgB[(i0+v)*L+k] * stgA[(i0+v)*196+k];
            ac0[v]=fmaf(rh,wc.x,ac0[v]); ac1[v]=fmaf(rh,wc.y,ac1[v]);
        }
    }
    #pragma unroll
    for(int v=0;v<8;v++) if(val[v]){
        int n = nid[v];
        float* A = stgA + (i0+v)*196;
        float co0 = tanhf(ac0[v]+scb[c0]);
        float co1 = tanhf(ac1[v]+scb[c0+1]);
        float hn0 = A[c0]   + z0[v]*co0;
        float hn1 = A[c0+1] + z1[v]*co1;
        g_H[n*L+c0]   = hn0;
        g_H[n*L+c0+1] = hn1;
    }
}

// ---------------- decode + enc/autoenc losses over a node list ----------------
#define DEC_SMEM (3*64*L*4)
__global__ __launch_bounds__(256) void k_decode(
        int mode, float lossW,
        const float* __restrict__ dW1, const float* __restrict__ db1,
        const float* __restrict__ dW2, const float* __restrict__ db2,
        const float* __restrict__ eW1, const float* __restrict__ eb1,
        const float* __restrict__ eW2, const float* __restrict__ eb2){
    int cnt = mode ? g_ndcount : g_drcount;
    if(blockIdx.x*64 >= cnt) return;
    const int* list = mode ? g_nd : g_dr;
    extern __shared__ float sm[];
    float* sHn = sm;            // [64][64]
    float* sB  = sm + 64*L;     // [64][64]
    float* sE  = sm + 2*64*L;   // [64][64]
    __shared__ float sdW2[L], sdb1[L], sE1[L], sEb1[L], sEb2[L];
    __shared__ double red[8];
    int tid = threadIdx.x;
    if(tid<L){ sdW2[tid]=dW2[tid]; sdb1[tid]=db1[tid]; sE1[tid]=eW1[tid];
               sEb1[tid]=eb1[tid]; sEb2[tid]=eb2[tid]; }
    __syncthreads();
    int lane = tid&31, w = tid>>5, c0 = 2*lane;
    int i0 = w*8, sb = blockIdx.x*64 + i0;
    float db2v = db2[0];
    int nid[8]; bool val[8];
    #pragma unroll
    for(int v=0;v<8;v++){
        int slot = sb+v; val[v] = (slot < cnt);
        nid[v] = val[v]? list[slot] : 0;
        float2 h = val[v]? *(const float2*)&g_H[nid[v]*L+c0] : make_float2(0.f,0.f);
        *(float2*)&sHn[(i0+v)*L+c0] = h;
    }
    __syncwarp();
    // decoder hidden + U
    float ad0[8],ad1[8];
    #pragma unroll
    for(int v=0;v<8;v++){ ad0[v]=sdb1[c0]; ad1[v]=sdb1[c0+1]; }
    for(int k=0;k<L;k++){
        float2 wd = __ldg((const float2*)&dW1[k*L+c0]);
        #pragma unroll
        for(int v=0;v<8;v++){
            float hk = sHn[(i0+v)*L+k];
            ad0[v]=fmaf(hk,wd.x,ad0[v]); ad1[v]=fmaf(hk,wd.y,ad1[v]);
        }
    }
    float Uv[8];
    #pragma unroll
    for(int v=0;v<8;v++){
        float pu = fmaxf(ad0[v],0.f)*sdW2[c0] + fmaxf(ad1[v],0.f)*sdW2[c0+1];
        for(int o=16;o;o>>=1) pu += __shfl_xor_sync(0xffffffffu, pu, o);
        Uv[v] = pu + db2v;
        if(val[v] && lane==0) g_U[nid[v]] = Uv[v];
        float eh0 = fmaxf(fmaf(Uv[v],sE1[c0],sEb1[c0]),0.f);
        float eh1 = fmaxf(fmaf(Uv[v],sE1[c0+1],sEb1[c0+1]),0.f);
        sB[(i0+v)*L+c0]=eh0; sB[(i0+v)*L+c0+1]=eh1;
    }
    __syncwarp();
    // enc(U)
    float ae0[8],ae1[8];
    #pragma unroll
    for(int v=0;v<8;v++){ ae0[v]=sEb2[c0]; ae1[v]=sEb2[c0+1]; }
    for(int k=0;k<L;k++){
        float2 we = __ldg((const float2*)&eW2[k*L+c0]);
        #pragma unroll
        for(int v=0;v<8;v++){
            float ek = sB[(i0+v)*L+k];
            ae0[v]=fmaf(ek,we.x,ae0[v]); ae1[v]=fmaf(ek,we.y,ae1[v]);
        }
    }
    float encS = 0.f;
    #pragma unroll
    for(int v=0;v<8;v++){
        if(val[v]){
            float d0 = ae0[v]-sHn[(i0+v)*L+c0], d1 = ae1[v]-sHn[(i0+v)*L+c0+1];
            encS += d0*d0 + d1*d1;
        }
        sE[(i0+v)*L+c0]=ae0[v]; sE[(i0+v)*L+c0+1]=ae1[v];
    }
    __syncwarp();
    // autoenc: dec(enc)
    float ag0[8],ag1[8];
    #pragma unroll
    for(int v=0;v<8;v++){ ag0[v]=sdb1[c0]; ag1[v]=sdb1[c0+1]; }
    for(int k=0;k<L;k++){
        float2 wd = __ldg((const float2*)&dW1[k*L+c0]);
        #pragma unroll
        for(int v=0;v<8;v++){
            float ek = sE[(i0+v)*L+k];
            ag0[v]=fmaf(ek,wd.x,ag0[v]); ag1[v]=fmaf(ek,wd.y,ag1[v]);
        }
    }
    float autoS = 0.f;
    #pragma unroll
    for(int v=0;v<8;v++){
        float pa = fmaxf(ag0[v],0.f)*sdW2[c0] + fmaxf(ag1[v],0.f)*sdW2[c0+1];
        for(int o=16;o;o>>=1) pa += __shfl_xor_sync(0xffffffffu, pa, o);
        float aout = pa + db2v;
        if(val[v] && lane==0){ float d = aout - Uv[v]; autoS += d*d; }
    }
    float tot = encS;
    for(int o=16;o;o>>=1) tot += __shfl_xor_sync(0xffffffffu, tot, o);
    float at = autoS;
    for(int o=16;o;o>>=1) at += __shfl_xor_sync(0xffffffffu, at, o);
    if(lane==0) red[w] = (double)lossW * ((double)tot/((double)NN*64.0) + (double)at/(double)NN);
    __syncthreads();
    if(tid==0){
        double s = 0.0;
        for(int i=0;i<8;i++) s += red[i];
        atomicAdd(&g_loss, s);
    }
}

// ---------------- residual loss ----------------
__global__ __launch_bounds__(256) void k_res(const float* __restrict__ y, float wgt){
    __shared__ double red[8];
    int lane = threadIdx.x&31, w = threadIdx.x>>5;
    int wid = blockIdx.x*8 + w;
    int nwarps = gridDim.x*8;
    float ls = 0.f;
    for(int n = wid; n < NN; n += nwarps){
        int s = g_rowptr[n], e = g_rowptr[n+1];
        float part = 0.f;
        for(int p = s+lane; p < e; p += 32){
            int j = __float_as_int(g_rowE4[p].w);
            part += g_rowA[p] * g_U[j];
        }
        for(int o=16;o;o>>=1) part += __shfl_xor_sync(0xffffffffu, part, o);
        if(lane==0){ float d = part - y[n]; ls += d*d; }
    }
    for(int o=16;o;o>>=1) ls += __shfl_xor_sync(0xffffffffu, ls, o);
    if(lane==0) red[w] = (double)ls;
    __syncthreads();
    if(threadIdx.x==0){
        double s=0.0; for(int i=0;i<8;i++) s+=red[i];
        atomicAdd(&g_loss, s * (double)wgt / (double)NN);
    }
}

// ---------------- finalize + reset state for next replay ----------------
__global__ void k_fin(float* __restrict__ out, int out_size){
    int i = blockIdx.x*blockDim.x + threadIdx.x;
    if(i < NN && i < out_size) out[i] = g_U[i];
    if(i == NN){
        if(i < out_size) out[NN] = (float)g_loss;
        g_loss = 0.0;
    }
    if(i < NN){ g_cntr[i]=0; g_cntc[i]=0; }
}

extern "C" void kernel_launch(void* const* d_in, const int* in_sizes, int n_in,
                              void* d_out, int out_size){
    const float* x    = (const float*)d_in[0];
    const float* y    = (const float*)d_in[2];
    const int*   tags = (const int*)  d_in[3];
    const int*   ei   = (const int*)  d_in[4];
    const float* ea   = (const float*)d_in[5];
    const float* aij  = (const float*)d_in[6];
    const float* prb  = (const float*)d_in[7];
    const float* ptW1 = (const float*)d_in[8];
    const float* ptb1 = (const float*)d_in[9];
    const float* ptW2 = (const float*)d_in[10];
    const float* ptb2 = (const float*)d_in[11];
    const float* pfW1 = (const float*)d_in[12];
    const float* pfb1 = (const float*)d_in[13];
    const float* pfW2 = (const float*)d_in[14];
    const float* pfb2 = (const float*)d_in[15];
    const float* zkW  = (const float*)d_in[16];
    const float* zkb  = (const float*)d_in[17];
    const float* rkW  = (const float*)d_in[18];
    const float* rkb  = (const float*)d_in[19];
    const float* cW   = (const float*)d_in[20];
    const float* cb   = (const float*)d_in[21];
    const float* eW1  = (const float*)d_in[22];
    const float* eb1  = (const float*)d_in[23];
    const float* eW2  = (const float*)d_in[24];
    const float* eb2  = (const float*)d_in[25];
    const float* dW1  = (const float*)d_in[26];
    const float* db1  = (const float*)d_in[27];
    const float* dW2  = (const float*)d_in[28];
    const float* db2  = (const float*)d_in[29];

    cudaFuncSetAttribute(k_prep,   cudaFuncAttributeMaxDynamicSharedMemorySize, PREP_SMEM);
    cudaFuncSetAttribute(k_gate,   cudaFuncAttributeMaxDynamicSharedMemorySize, GATE_SMEM);
    cudaFuncSetAttribute(k_decode, cudaFuncAttributeMaxDynamicSharedMemorySize, DEC_SMEM);

    int *rowptr, *colptr;
    float4 *rowE4, *colE4;
    float *Pt, *Qt, *Pf, *Qf, *mt, *mf;
    cudaGetSymbolAddress((void**)&rowptr, g_rowptr);
    cudaGetSymbolAddress((void**)&colptr, g_colptr);
    cudaGetSymbolAddress((void**)&rowE4,  g_rowE4);
    cudaGetSymbolAddress((void**)&colE4,  g_colE4);
    cudaGetSymbolAddress((void**)&Pt, g_Pt);
    cudaGetSymbolAddress((void**)&Qt, g_Qt);
    cudaGetSymbolAddress((void**)&Pf, g_Pf);
    cudaGetSymbolAddress((void**)&Qf, g_Qf);
    cudaGetSymbolAddress((void**)&mt, g_mt);
    cudaGetSymbolAddress((void**)&mf, g_mf);

    k_enc0<<<NB32, 256>>>(x, eW1, eb1, eW2, eb2);                        // 0
    k_hist<<<(NE+255)/256, 256>>>(ei);                                   // 1
    k_scan<<<1, 1024>>>(tags);                                           // 2
    k_prep<<<NB64, 256, PREP_SMEM>>>(ptW1, ptb1, pfW1, pfb1, 0);         // 3 (profiled)
    k_scatter<<<(NE+255)/256, 256>>>(ei, ea, aij);                       // 4
    // Dirichlet nodes: U + enc/autoenc losses are identical both steps -> once, weight 2
    k_decode<<<NB64, 256, DEC_SMEM>>>(0, 2.0f, dW1, db1, dW2, db2, eW1, eb1, eW2, eb2);

    const float gammaw[2] = {0.9f, 1.0f};
    for(int step=0; step<2; step++){
        k_aggr<<<2*NB32, 256>>>(colptr, colE4, rowptr, rowE4,
                                Pt, Qt, Pf, Qf,
                                ptW1, ptb2, ptW2, pfW1, pfb2, pfW2, mt, mf);
        k_gate<<<NB64, 256, GATE_SMEM>>>(prb, zkW, zkb, rkW, rkb, cW, cb);
        k_decode<<<NB64, 256, DEC_SMEM>>>(1, 1.0f, dW1, db1, dW2, db2, eW1, eb1, eW2, eb2);
        k_res<<<NB32, 256>>>(y, gammaw[step]);
        if(step == 0)
            k_prep<<<NB64, 256, PREP_SMEM>>>(ptW1, ptb1, pfW1, pfb1, 1);  // only changed H
    }
    k_fin<<<(NN+256)/256, 256>>>((float*)d_out, out_size);
}